// round 1
// baseline (speedup 1.0000x reference)
#include <cuda_runtime.h>
#include <math.h>

#define BATCH 2
#define SEQ 2048
#define DMODEL 1024
#define NH 16
#define DH 64
#define MTOT (BATCH*SEQ)

// Scratch (device globals; no allocations allowed)
__device__ float g_Q[BATCH*NH*SEQ*DH];
__device__ float g_K[BATCH*NH*SEQ*DH];
__device__ float g_V[BATCH*NH*SEQ*DH];
__device__ float g_att[(size_t)MTOT*DMODEL];

// ---------------------------------------------------------------------------
// GEMM: Y = X (M x 1024) @ W^T, W is (1024 x 1024) row-major.
// Block tile 128x128, K-step 16, 256 threads, 8x8 register micro-tile.
// HEADOUT=1: write into [B,H,S,Dh] head-major layout (for Q/K/V projections).
// HEADOUT=0: plain row-major [M,1024] (for the output projection).
// ---------------------------------------------------------------------------
template<int HEADOUT>
__global__ __launch_bounds__(256)
void gemm_xwT(const float* __restrict__ X, const float* __restrict__ W,
              float* __restrict__ Y)
{
    __shared__ float As[16][132];   // [k][m], padded (132*4B = 33*16B)
    __shared__ float Bs[16][132];   // [k][n]
    const int tid = threadIdx.x;
    const int tx = tid & 15, ty = tid >> 4;
    const int m0 = blockIdx.x * 128;
    const int n0 = blockIdx.y * 128;

    float acc[8][8];
#pragma unroll
    for (int i = 0; i < 8; i++)
#pragma unroll
        for (int j = 0; j < 8; j++) acc[i][j] = 0.f;

    for (int k0 = 0; k0 < DMODEL; k0 += 16) {
#pragma unroll
        for (int i = 0; i < 2; i++) {
            int f = tid + i * 256;          // 0..511
            int r = f >> 2;                 // 0..127
            int kq = (f & 3) << 2;          // 0,4,8,12
            float4 a = *(const float4*)&X[(size_t)(m0 + r) * DMODEL + k0 + kq];
            As[kq + 0][r] = a.x; As[kq + 1][r] = a.y;
            As[kq + 2][r] = a.z; As[kq + 3][r] = a.w;
            float4 b = *(const float4*)&W[(size_t)(n0 + r) * DMODEL + k0 + kq];
            Bs[kq + 0][r] = b.x; Bs[kq + 1][r] = b.y;
            Bs[kq + 2][r] = b.z; Bs[kq + 3][r] = b.w;
        }
        __syncthreads();
#pragma unroll
        for (int kk = 0; kk < 16; kk++) {
            float4 a0 = *(const float4*)&As[kk][ty * 8];
            float4 a1 = *(const float4*)&As[kk][ty * 8 + 4];
            float4 b0 = *(const float4*)&Bs[kk][tx * 8];
            float4 b1 = *(const float4*)&Bs[kk][tx * 8 + 4];
            float av[8] = {a0.x, a0.y, a0.z, a0.w, a1.x, a1.y, a1.z, a1.w};
            float bv[8] = {b0.x, b0.y, b0.z, b0.w, b1.x, b1.y, b1.z, b1.w};
#pragma unroll
            for (int i = 0; i < 8; i++)
#pragma unroll
                for (int j = 0; j < 8; j++)
                    acc[i][j] = fmaf(av[i], bv[j], acc[i][j]);
        }
        __syncthreads();
    }

#pragma unroll
    for (int i = 0; i < 8; i++) {
        int mg = m0 + ty * 8 + i;
        float4 v0 = make_float4(acc[i][0], acc[i][1], acc[i][2], acc[i][3]);
        float4 v1 = make_float4(acc[i][4], acc[i][5], acc[i][6], acc[i][7]);
        if (HEADOUT) {
            int b = mg >> 11;               // / SEQ
            int s = mg & (SEQ - 1);
            int ng = n0 + tx * 8;           // 8 cols stay inside one head
            int h = ng >> 6, d0 = ng & 63;
            float* dst = Y + ((size_t)((b << 4) + h) * SEQ + s) * DH + d0;
            *(float4*)dst = v0;
            *(float4*)(dst + 4) = v1;
        } else {
            float* dst = Y + (size_t)mg * DMODEL + n0 + tx * 8;
            *(float4*)dst = v0;
            *(float4*)(dst + 4) = v1;
        }
    }
}

// ---------------------------------------------------------------------------
// RoPE in-place on g_Q / g_K. One thread per (b,h,s,pair).
// Angle computed in double (more accurate than the reference's own fp32).
// ---------------------------------------------------------------------------
__global__ void rope_kernel()
{
    int idx = blockIdx.x * blockDim.x + threadIdx.x;
    if (idx >= BATCH * NH * SEQ * 32) return;
    int p = idx & 31;
    int s = (idx >> 5) & (SEQ - 1);
    int bh = idx >> 16;                     // 32*2048 = 2^16
    double inv = pow(10000.0, -(double)p / 32.0);
    double ang = (double)s * inv;
    double sd, cd;
    sincos(ang, &sd, &cd);
    float c = (float)cd, sn = (float)sd;
    size_t base = ((size_t)bh * SEQ + s) * DH;
    float q1 = g_Q[base + p], q2 = g_Q[base + p + 32];
    g_Q[base + p]      = q1 * c - q2 * sn;
    g_Q[base + p + 32] = q2 * c + q1 * sn;
    float k1 = g_K[base + p], k2 = g_K[base + p + 32];
    g_K[base + p]      = k1 * c - k2 * sn;
    g_K[base + p + 32] = k2 * c + k1 * sn;
}

// ---------------------------------------------------------------------------
// Flash attention (causal). CTA = (q-tile of 128, b*h). 256 threads.
// K-tile = 64. S micro-tile 8x4 per thread (16x16 thread grid).
// Smem: Qs[d][q] 64x132, Ks[d][j] 64x68, Vs[j][d] 64x64, Ps[j][q] 64x132.
// ---------------------------------------------------------------------------
__global__ __launch_bounds__(256)
void attn_kernel()
{
    extern __shared__ float sm[];
    float* Qs = sm;                 // 64*132
    float* Ks = Qs + 64 * 132;      // 64*68
    float* Vs = Ks + 64 * 68;       // 64*64
    float* Ps = Vs + 64 * 64;       // 64*132

    const int qt = blockIdx.x;
    const int bh = blockIdx.y;
    const int q0 = qt * 128;
    const int b = bh >> 4, h = bh & 15;
    const float* Qg = g_Q + ((size_t)bh * SEQ + q0) * DH;
    const float* Kg = g_K + (size_t)bh * SEQ * DH;
    const float* Vg = g_V + (size_t)bh * SEQ * DH;

    const int tid = threadIdx.x;
    const int tx = tid & 15, ty = tid >> 4;

    // Load Q tile transposed: Qs[d][r]
#pragma unroll
    for (int i = 0; i < 8; i++) {
        int f = tid + i * 256;              // 0..2047
        int r = f >> 4;                     // 0..127
        int d = (f & 15) << 2;
        float4 v = *(const float4*)&Qg[r * DH + d];
        Qs[(d + 0) * 132 + r] = v.x;
        Qs[(d + 1) * 132 + r] = v.y;
        Qs[(d + 2) * 132 + r] = v.z;
        Qs[(d + 3) * 132 + r] = v.w;
    }

    float m_i[8], l_i[8], o[8][4];
#pragma unroll
    for (int i = 0; i < 8; i++) {
        m_i[i] = -1e30f; l_i[i] = 0.f;
#pragma unroll
        for (int c = 0; c < 4; c++) o[i][c] = 0.f;
    }

    const int nt = qt * 2 + 2;              // causal tile count
    for (int t = 0; t < nt; t++) {
        const int j0 = t * 64;
        // Load K (transposed) and V (natural)
#pragma unroll
        for (int i = 0; i < 4; i++) {
            int f = tid + i * 256;          // 0..1023
            int r = f >> 4;                 // 0..63
            int d = (f & 15) << 2;
            float4 kv = *(const float4*)&Kg[(size_t)(j0 + r) * DH + d];
            Ks[(d + 0) * 68 + r] = kv.x;
            Ks[(d + 1) * 68 + r] = kv.y;
            Ks[(d + 2) * 68 + r] = kv.z;
            Ks[(d + 3) * 68 + r] = kv.w;
            float4 vv = *(const float4*)&Vg[(size_t)(j0 + r) * DH + d];
            *(float4*)&Vs[r * DH + d] = vv;
        }
        __syncthreads();

        // S = Q @ K^T (8x4 per thread)
        float sacc[8][4];
#pragma unroll
        for (int i = 0; i < 8; i++)
#pragma unroll
            for (int c = 0; c < 4; c++) sacc[i][c] = 0.f;

#pragma unroll 8
        for (int d = 0; d < 64; d++) {
            float4 qa = *(const float4*)&Qs[d * 132 + ty * 8];
            float4 qb = *(const float4*)&Qs[d * 132 + ty * 8 + 4];
            float4 kv = *(const float4*)&Ks[d * 68 + tx * 4];
            float av[8] = {qa.x, qa.y, qa.z, qa.w, qb.x, qb.y, qb.z, qb.w};
            float bv[4] = {kv.x, kv.y, kv.z, kv.w};
#pragma unroll
            for (int i = 0; i < 8; i++)
#pragma unroll
                for (int c = 0; c < 4; c++)
                    sacc[i][c] = fmaf(av[i], bv[c], sacc[i][c]);
        }

        // Online softmax; rows are split across the 16 tx lanes -> shfl reduce
#pragma unroll
        for (int i = 0; i < 8; i++) {
            const int row = q0 + ty * 8 + i;
            float sv[4];
#pragma unroll
            for (int c = 0; c < 4; c++) {
                int col = j0 + tx * 4 + c;
                sv[c] = (col <= row) ? sacc[i][c] * 0.125f : -1e30f;
            }
            float mx = fmaxf(fmaxf(sv[0], sv[1]), fmaxf(sv[2], sv[3]));
            mx = fmaxf(mx, __shfl_xor_sync(0xffffffffu, mx, 1));
            mx = fmaxf(mx, __shfl_xor_sync(0xffffffffu, mx, 2));
            mx = fmaxf(mx, __shfl_xor_sync(0xffffffffu, mx, 4));
            mx = fmaxf(mx, __shfl_xor_sync(0xffffffffu, mx, 8));
            float mnew = fmaxf(m_i[i], mx);
            float alpha = __expf(m_i[i] - mnew);
            m_i[i] = mnew;
            float p0 = __expf(sv[0] - mnew);
            float p1 = __expf(sv[1] - mnew);
            float p2 = __expf(sv[2] - mnew);
            float p3 = __expf(sv[3] - mnew);
            float rs = p0 + p1 + p2 + p3;
            rs += __shfl_xor_sync(0xffffffffu, rs, 1);
            rs += __shfl_xor_sync(0xffffffffu, rs, 2);
            rs += __shfl_xor_sync(0xffffffffu, rs, 4);
            rs += __shfl_xor_sync(0xffffffffu, rs, 8);
            l_i[i] = l_i[i] * alpha + rs;
#pragma unroll
            for (int c = 0; c < 4; c++) o[i][c] *= alpha;
            // Stage P transposed for the PV GEMM: Ps[j][r]
            Ps[(tx * 4 + 0) * 132 + ty * 8 + i] = p0;
            Ps[(tx * 4 + 1) * 132 + ty * 8 + i] = p1;
            Ps[(tx * 4 + 2) * 132 + ty * 8 + i] = p2;
            Ps[(tx * 4 + 3) * 132 + ty * 8 + i] = p3;
        }
        __syncthreads();

        // O += P @ V
#pragma unroll 8
        for (int k = 0; k < 64; k++) {
            float4 pa = *(const float4*)&Ps[k * 132 + ty * 8];
            float4 pb = *(const float4*)&Ps[k * 132 + ty * 8 + 4];
            float4 vv = *(const float4*)&Vs[k * DH + tx * 4];
            float pv[8] = {pa.x, pa.y, pa.z, pa.w, pb.x, pb.y, pb.z, pb.w};
#pragma unroll
            for (int i = 0; i < 8; i++) {
                o[i][0] = fmaf(pv[i], vv.x, o[i][0]);
                o[i][1] = fmaf(pv[i], vv.y, o[i][1]);
                o[i][2] = fmaf(pv[i], vv.z, o[i][2]);
                o[i][3] = fmaf(pv[i], vv.w, o[i][3]);
            }
        }
        __syncthreads();
    }

    // Epilogue: write [B,S,D] so the output projection reads row-major
#pragma unroll
    for (int i = 0; i < 8; i++) {
        float invl = 1.f / l_i[i];
        int srow = q0 + ty * 8 + i;
        float4 v = make_float4(o[i][0] * invl, o[i][1] * invl,
                               o[i][2] * invl, o[i][3] * invl);
        *(float4*)&g_att[((size_t)b * SEQ + srow) * DMODEL + h * DH + tx * 4] = v;
    }
}

// ---------------------------------------------------------------------------
// Launch. Inputs: 0=x, 1=attn_mask (always causal -> unused), 2..5 = Wq,Wk,Wv,Wo
// ---------------------------------------------------------------------------
extern "C" void kernel_launch(void* const* d_in, const int* in_sizes, int n_in,
                              void* d_out, int out_size)
{
    const float* x  = (const float*)d_in[0];
    const float* Wq = (const float*)d_in[2];
    const float* Wk = (const float*)d_in[3];
    const float* Wv = (const float*)d_in[4];
    const float* Wo = (const float*)d_in[5];
    float* out = (float*)d_out;

    float *qp, *kp, *vp, *ap;
    cudaGetSymbolAddress((void**)&qp, g_Q);
    cudaGetSymbolAddress((void**)&kp, g_K);
    cudaGetSymbolAddress((void**)&vp, g_V);
    cudaGetSymbolAddress((void**)&ap, g_att);

    dim3 gg(MTOT / 128, DMODEL / 128);
    gemm_xwT<1><<<gg, 256>>>(x, Wq, qp);
    gemm_xwT<1><<<gg, 256>>>(x, Wk, kp);
    gemm_xwT<1><<<gg, 256>>>(x, Wv, vp);

    int nrope = BATCH * NH * SEQ * 32;
    rope_kernel<<<(nrope + 255) / 256, 256>>>();

    int smem = 64 * (132 + 68 + 64 + 132) * (int)sizeof(float);
    cudaFuncSetAttribute(attn_kernel,
                         cudaFuncAttributeMaxDynamicSharedMemorySize, smem);
    attn_kernel<<<dim3(SEQ / 128, BATCH * NH), 256, smem>>>();

    gemm_xwT<0><<<gg, 256>>>(ap, Wo, out);
}

// round 2
// speedup vs baseline: 1.2859x; 1.2859x over previous
#include <cuda_runtime.h>
#include <math.h>

#define BATCH 2
#define SEQ 2048
#define DMODEL 1024
#define NH 16
#define DH 64
#define MTOT (BATCH*SEQ)

// Scratch (device globals; no allocations allowed)
__device__ float g_Q[BATCH*NH*SEQ*DH];
__device__ float g_K[BATCH*NH*SEQ*DH];
__device__ float g_V[BATCH*NH*SEQ*DH];
__device__ float g_att[(size_t)MTOT*DMODEL];
__device__ float g_cos[SEQ*32];
__device__ float g_sin[SEQ*32];

// ---------------------------------------------------------------------------
// RoPE table: cos/sin[s][p], p = frequency index 0..31. Double math once.
// ---------------------------------------------------------------------------
__global__ void rope_table_kernel()
{
    int idx = blockIdx.x * blockDim.x + threadIdx.x;
    if (idx >= SEQ * 32) return;
    int p = idx & 31;
    int s = idx >> 5;
    double inv = pow(10000.0, -(double)p / 32.0);
    double sd, cd;
    sincos((double)s * inv, &sd, &cd);
    g_cos[idx] = (float)cd;
    g_sin[idx] = (float)sd;
}

// ---------------------------------------------------------------------------
// RoPE apply (vectorized, memory-bound). One thread = 4 pairs for Q and K.
// ---------------------------------------------------------------------------
__global__ void rope_apply_kernel()
{
    int t = blockIdx.x * blockDim.x + threadIdx.x;
    if (t >= BATCH * NH * SEQ * 8) return;
    int pq = t & 7;                       // which float4 of the 32 pairs
    int s = (t >> 3) & (SEQ - 1);
    int bh = t >> 14;
    float4 c = *(const float4*)&g_cos[s * 32 + pq * 4];
    float4 sn = *(const float4*)&g_sin[s * 32 + pq * 4];
    size_t base = ((size_t)bh * SEQ + s) * DH + pq * 4;

    float4 q1 = *(const float4*)&g_Q[base];
    float4 q2 = *(const float4*)&g_Q[base + 32];
    float4 r1, r2;
    r1.x = q1.x * c.x - q2.x * sn.x;  r2.x = q2.x * c.x + q1.x * sn.x;
    r1.y = q1.y * c.y - q2.y * sn.y;  r2.y = q2.y * c.y + q1.y * sn.y;
    r1.z = q1.z * c.z - q2.z * sn.z;  r2.z = q2.z * c.z + q1.z * sn.z;
    r1.w = q1.w * c.w - q2.w * sn.w;  r2.w = q2.w * c.w + q1.w * sn.w;
    *(float4*)&g_Q[base] = r1;
    *(float4*)&g_Q[base + 32] = r2;

    float4 k1 = *(const float4*)&g_K[base];
    float4 k2 = *(const float4*)&g_K[base + 32];
    r1.x = k1.x * c.x - k2.x * sn.x;  r2.x = k2.x * c.x + k1.x * sn.x;
    r1.y = k1.y * c.y - k2.y * sn.y;  r2.y = k2.y * c.y + k1.y * sn.y;
    r1.z = k1.z * c.z - k2.z * sn.z;  r2.z = k2.z * c.z + k1.z * sn.z;
    r1.w = k1.w * c.w - k2.w * sn.w;  r2.w = k2.w * c.w + k1.w * sn.w;
    *(float4*)&g_K[base] = r1;
    *(float4*)&g_K[base + 32] = r2;
}

// ---------------------------------------------------------------------------
// GEMM: Y = X (M x 1024) @ W^T, W row-major [1024,1024].
// 128x128 block tile, K-step 16, 256 threads, 8x8 micro-tile.
// Double-buffered smem with register prefetch.
// QKV=1: blockIdx.z selects Wq/Wk/Wv and writes [B,H,S,Dh] head layout.
// QKV=0: plain row-major output (output projection).
// ---------------------------------------------------------------------------
template<int QKV>
__global__ __launch_bounds__(256)
void gemm_xwT(const float* __restrict__ X,
              const float* __restrict__ W0, const float* __restrict__ W1,
              const float* __restrict__ W2,
              float* __restrict__ Y0, float* __restrict__ Y1,
              float* __restrict__ Y2)
{
    __shared__ float As[2][16][132];
    __shared__ float Bs[2][16][132];
    const int tid = threadIdx.x;
    const int tx = tid & 15, ty = tid >> 4;
    const int m0 = blockIdx.x * 128;
    const int n0 = blockIdx.y * 128;
    const float* W = W0;
    float* Y = Y0;
    if (QKV) {
        if (blockIdx.z == 1) { W = W1; Y = Y1; }
        else if (blockIdx.z == 2) { W = W2; Y = Y2; }
    }

    // Per-thread load coords (2 rows of 4 k-values each)
    const int r0 = tid >> 2;               // 0..63
    const int kq = (tid & 3) << 2;         // 0,4,8,12
    const float* Xp = X + (size_t)(m0 + r0) * DMODEL + kq;
    const float* Wp = W + (size_t)(n0 + r0) * DMODEL + kq;
    const float* Xp2 = Xp + 64 * DMODEL;
    const float* Wp2 = Wp + 64 * DMODEL;

    float acc[8][8];
#pragma unroll
    for (int i = 0; i < 8; i++)
#pragma unroll
        for (int j = 0; j < 8; j++) acc[i][j] = 0.f;

    // Preload tile 0
    float4 ax0 = *(const float4*)Xp,  ax1 = *(const float4*)Xp2;
    float4 bx0 = *(const float4*)Wp,  bx1 = *(const float4*)Wp2;
    {
        As[0][kq+0][r0] = ax0.x; As[0][kq+1][r0] = ax0.y;
        As[0][kq+2][r0] = ax0.z; As[0][kq+3][r0] = ax0.w;
        As[0][kq+0][r0+64] = ax1.x; As[0][kq+1][r0+64] = ax1.y;
        As[0][kq+2][r0+64] = ax1.z; As[0][kq+3][r0+64] = ax1.w;
        Bs[0][kq+0][r0] = bx0.x; Bs[0][kq+1][r0] = bx0.y;
        Bs[0][kq+2][r0] = bx0.z; Bs[0][kq+3][r0] = bx0.w;
        Bs[0][kq+0][r0+64] = bx1.x; Bs[0][kq+1][r0+64] = bx1.y;
        Bs[0][kq+2][r0+64] = bx1.z; Bs[0][kq+3][r0+64] = bx1.w;
    }
    __syncthreads();

    int buf = 0;
    for (int k0 = 16; k0 <= DMODEL; k0 += 16) {
        const bool more = (k0 < DMODEL);
        if (more) {
            ax0 = *(const float4*)(Xp + k0);
            ax1 = *(const float4*)(Xp2 + k0);
            bx0 = *(const float4*)(Wp + k0);
            bx1 = *(const float4*)(Wp2 + k0);
        }
#pragma unroll
        for (int kk = 0; kk < 16; kk++) {
            float4 a0 = *(const float4*)&As[buf][kk][ty * 8];
            float4 a1 = *(const float4*)&As[buf][kk][ty * 8 + 4];
            float4 b0 = *(const float4*)&Bs[buf][kk][tx * 8];
            float4 b1 = *(const float4*)&Bs[buf][kk][tx * 8 + 4];
            float av[8] = {a0.x, a0.y, a0.z, a0.w, a1.x, a1.y, a1.z, a1.w};
            float bv[8] = {b0.x, b0.y, b0.z, b0.w, b1.x, b1.y, b1.z, b1.w};
#pragma unroll
            for (int i = 0; i < 8; i++)
#pragma unroll
                for (int j = 0; j < 8; j++)
                    acc[i][j] = fmaf(av[i], bv[j], acc[i][j]);
        }
        if (more) {
            int nb = buf ^ 1;
            As[nb][kq+0][r0] = ax0.x; As[nb][kq+1][r0] = ax0.y;
            As[nb][kq+2][r0] = ax0.z; As[nb][kq+3][r0] = ax0.w;
            As[nb][kq+0][r0+64] = ax1.x; As[nb][kq+1][r0+64] = ax1.y;
            As[nb][kq+2][r0+64] = ax1.z; As[nb][kq+3][r0+64] = ax1.w;
            Bs[nb][kq+0][r0] = bx0.x; Bs[nb][kq+1][r0] = bx0.y;
            Bs[nb][kq+2][r0] = bx0.z; Bs[nb][kq+3][r0] = bx0.w;
            Bs[nb][kq+0][r0+64] = bx1.x; Bs[nb][kq+1][r0+64] = bx1.y;
            Bs[nb][kq+2][r0+64] = bx1.z; Bs[nb][kq+3][r0+64] = bx1.w;
            __syncthreads();
        }
        buf ^= 1;
    }

#pragma unroll
    for (int i = 0; i < 8; i++) {
        int mg = m0 + ty * 8 + i;
        float4 v0 = make_float4(acc[i][0], acc[i][1], acc[i][2], acc[i][3]);
        float4 v1 = make_float4(acc[i][4], acc[i][5], acc[i][6], acc[i][7]);
        if (QKV) {
            int b = mg >> 11;
            int s = mg & (SEQ - 1);
            int ng = n0 + tx * 8;
            int h = ng >> 6, d0 = ng & 63;
            float* dst = Y + ((size_t)((b << 4) + h) * SEQ + s) * DH + d0;
            *(float4*)dst = v0;
            *(float4*)(dst + 4) = v1;
        } else {
            float* dst = Y + (size_t)mg * DMODEL + n0 + tx * 8;
            *(float4*)dst = v0;
            *(float4*)(dst + 4) = v1;
        }
    }
}

// ---------------------------------------------------------------------------
// Flash attention (causal). CTA = (q-tile of 128, b*h). 256 threads.
// ---------------------------------------------------------------------------
__global__ __launch_bounds__(256)
void attn_kernel()
{
    extern __shared__ float sm[];
    float* Qs = sm;                 // 64*132
    float* Ks = Qs + 64 * 132;      // 64*68
    float* Vs = Ks + 64 * 68;       // 64*64
    float* Ps = Vs + 64 * 64;       // 64*132

    const int qt = blockIdx.x;
    const int bh = blockIdx.y;
    const int q0 = qt * 128;
    const int b = bh >> 4, h = bh & 15;
    const float* Qg = g_Q + ((size_t)bh * SEQ + q0) * DH;
    const float* Kg = g_K + (size_t)bh * SEQ * DH;
    const float* Vg = g_V + (size_t)bh * SEQ * DH;

    const int tid = threadIdx.x;
    const int tx = tid & 15, ty = tid >> 4;

#pragma unroll
    for (int i = 0; i < 8; i++) {
        int f = tid + i * 256;
        int r = f >> 4;
        int d = (f & 15) << 2;
        float4 v = *(const float4*)&Qg[r * DH + d];
        Qs[(d + 0) * 132 + r] = v.x;
        Qs[(d + 1) * 132 + r] = v.y;
        Qs[(d + 2) * 132 + r] = v.z;
        Qs[(d + 3) * 132 + r] = v.w;
    }

    float m_i[8], l_i[8], o[8][4];
#pragma unroll
    for (int i = 0; i < 8; i++) {
        m_i[i] = -1e30f; l_i[i] = 0.f;
#pragma unroll
        for (int c = 0; c < 4; c++) o[i][c] = 0.f;
    }

    const int nt = qt * 2 + 2;
    for (int t = 0; t < nt; t++) {
        const int j0 = t * 64;
#pragma unroll
        for (int i = 0; i < 4; i++) {
            int f = tid + i * 256;
            int r = f >> 4;
            int d = (f & 15) << 2;
            float4 kv = *(const float4*)&Kg[(size_t)(j0 + r) * DH + d];
            Ks[(d + 0) * 68 + r] = kv.x;
            Ks[(d + 1) * 68 + r] = kv.y;
            Ks[(d + 2) * 68 + r] = kv.z;
            Ks[(d + 3) * 68 + r] = kv.w;
            float4 vv = *(const float4*)&Vg[(size_t)(j0 + r) * DH + d];
            *(float4*)&Vs[r * DH + d] = vv;
        }
        __syncthreads();

        float sacc[8][4];
#pragma unroll
        for (int i = 0; i < 8; i++)
#pragma unroll
            for (int c = 0; c < 4; c++) sacc[i][c] = 0.f;

#pragma unroll 8
        for (int d = 0; d < 64; d++) {
            float4 qa = *(const float4*)&Qs[d * 132 + ty * 8];
            float4 qb = *(const float4*)&Qs[d * 132 + ty * 8 + 4];
            float4 kv = *(const float4*)&Ks[d * 68 + tx * 4];
            float av[8] = {qa.x, qa.y, qa.z, qa.w, qb.x, qb.y, qb.z, qb.w};
            float bv[4] = {kv.x, kv.y, kv.z, kv.w};
#pragma unroll
            for (int i = 0; i < 8; i++)
#pragma unroll
                for (int c = 0; c < 4; c++)
                    sacc[i][c] = fmaf(av[i], bv[c], sacc[i][c]);
        }

#pragma unroll
        for (int i = 0; i < 8; i++) {
            const int row = q0 + ty * 8 + i;
            float sv[4];
#pragma unroll
            for (int c = 0; c < 4; c++) {
                int col = j0 + tx * 4 + c;
                sv[c] = (col <= row) ? sacc[i][c] * 0.125f : -1e30f;
            }
            float mx = fmaxf(fmaxf(sv[0], sv[1]), fmaxf(sv[2], sv[3]));
            mx = fmaxf(mx, __shfl_xor_sync(0xffffffffu, mx, 1));
            mx = fmaxf(mx, __shfl_xor_sync(0xffffffffu, mx, 2));
            mx = fmaxf(mx, __shfl_xor_sync(0xffffffffu, mx, 4));
            mx = fmaxf(mx, __shfl_xor_sync(0xffffffffu, mx, 8));
            float mnew = fmaxf(m_i[i], mx);
            float alpha = __expf(m_i[i] - mnew);
            m_i[i] = mnew;
            float p0 = __expf(sv[0] - mnew);
            float p1 = __expf(sv[1] - mnew);
            float p2 = __expf(sv[2] - mnew);
            float p3 = __expf(sv[3] - mnew);
            float rs = p0 + p1 + p2 + p3;
            rs += __shfl_xor_sync(0xffffffffu, rs, 1);
            rs += __shfl_xor_sync(0xffffffffu, rs, 2);
            rs += __shfl_xor_sync(0xffffffffu, rs, 4);
            rs += __shfl_xor_sync(0xffffffffu, rs, 8);
            l_i[i] = l_i[i] * alpha + rs;
#pragma unroll
            for (int c = 0; c < 4; c++) o[i][c] *= alpha;
            Ps[(tx * 4 + 0) * 132 + ty * 8 + i] = p0;
            Ps[(tx * 4 + 1) * 132 + ty * 8 + i] = p1;
            Ps[(tx * 4 + 2) * 132 + ty * 8 + i] = p2;
            Ps[(tx * 4 + 3) * 132 + ty * 8 + i] = p3;
        }
        __syncthreads();

#pragma unroll 8
        for (int k = 0; k < 64; k++) {
            float4 pa = *(const float4*)&Ps[k * 132 + ty * 8];
            float4 pb = *(const float4*)&Ps[k * 132 + ty * 8 + 4];
            float4 vv = *(const float4*)&Vs[k * DH + tx * 4];
            float pv[8] = {pa.x, pa.y, pa.z, pa.w, pb.x, pb.y, pb.z, pb.w};
#pragma unroll
            for (int i = 0; i < 8; i++) {
                o[i][0] = fmaf(pv[i], vv.x, o[i][0]);
                o[i][1] = fmaf(pv[i], vv.y, o[i][1]);
                o[i][2] = fmaf(pv[i], vv.z, o[i][2]);
                o[i][3] = fmaf(pv[i], vv.w, o[i][3]);
            }
        }
        __syncthreads();
    }

#pragma unroll
    for (int i = 0; i < 8; i++) {
        float invl = 1.f / l_i[i];
        int srow = q0 + ty * 8 + i;
        float4 v = make_float4(o[i][0] * invl, o[i][1] * invl,
                               o[i][2] * invl, o[i][3] * invl);
        *(float4*)&g_att[((size_t)b * SEQ + srow) * DMODEL + h * DH + tx * 4] = v;
    }
}

// ---------------------------------------------------------------------------
// Launch. Inputs: 0=x, 1=attn_mask (causal -> unused), 2..5 = Wq,Wk,Wv,Wo
// ---------------------------------------------------------------------------
extern "C" void kernel_launch(void* const* d_in, const int* in_sizes, int n_in,
                              void* d_out, int out_size)
{
    const float* x  = (const float*)d_in[0];
    const float* Wq = (const float*)d_in[2];
    const float* Wk = (const float*)d_in[3];
    const float* Wv = (const float*)d_in[4];
    const float* Wo = (const float*)d_in[5];
    float* out = (float*)d_out;

    float *qp, *kp, *vp, *ap;
    cudaGetSymbolAddress((void**)&qp, g_Q);
    cudaGetSymbolAddress((void**)&kp, g_K);
    cudaGetSymbolAddress((void**)&vp, g_V);
    cudaGetSymbolAddress((void**)&ap, g_att);

    rope_table_kernel<<<(SEQ * 32 + 255) / 256, 256>>>();

    dim3 gqkv(MTOT / 128, DMODEL / 128, 3);
    gemm_xwT<1><<<gqkv, 256>>>(x, Wq, Wk, Wv, qp, kp, vp);

    int nrope = BATCH * NH * SEQ * 8;
    rope_apply_kernel<<<(nrope + 255) / 256, 256>>>();

    int smem = 64 * (132 + 68 + 64 + 132) * (int)sizeof(float);
    cudaFuncSetAttribute(attn_kernel,
                         cudaFuncAttributeMaxDynamicSharedMemorySize, smem);
    attn_kernel<<<dim3(SEQ / 128, BATCH * NH), 256, smem>>>();

    dim3 go(MTOT / 128, DMODEL / 128, 1);
    gemm_xwT<0><<<go, 256>>>(ap, Wo, nullptr, nullptr, out, nullptr, nullptr);
}

// round 4
// speedup vs baseline: 1.6541x; 1.2863x over previous
#include <cuda_runtime.h>
#include <cuda_bf16.h>
#include <math.h>
#include <stdint.h>

#define BATCH 2
#define SEQ 2048
#define DMODEL 1024
#define NH 16
#define DH 64
#define MTOT (BATCH*SEQ)

// ---------------------------------------------------------------------------
// Device global scratch
// ---------------------------------------------------------------------------
__device__ __align__(128) float g_Q[BATCH*NH*SEQ*DH];
__device__ __align__(128) float g_K[BATCH*NH*SEQ*DH];
__device__ __align__(128) float g_V[BATCH*NH*SEQ*DH];
__device__ __align__(128) float g_att[(size_t)MTOT*DMODEL];
__device__ float g_cos[SEQ*32];
__device__ float g_sin[SEQ*32];
// bf16 split buffers: [rows][2048], cols 0..1023 = hi, 1024..2047 = lo
__device__ __align__(128) __nv_bfloat16 g_Xcat[(size_t)MTOT*2048];
__device__ __align__(128) __nv_bfloat16 g_Acat[(size_t)MTOT*2048];
__device__ __align__(128) __nv_bfloat16 g_Wqc[1024*2048];
__device__ __align__(128) __nv_bfloat16 g_Wkc[1024*2048];
__device__ __align__(128) __nv_bfloat16 g_Wvc[1024*2048];
__device__ __align__(128) __nv_bfloat16 g_Woc[1024*2048];

__device__ __forceinline__ uint32_t smem_u32(const void* p) {
    uint32_t a;
    asm("{ .reg .u64 t; cvta.to.shared.u64 t, %1; cvt.u32.u64 %0, t; }"
        : "=r"(a) : "l"(p));
    return a;
}
#define CP_ASYNC16(dst, src) \
    asm volatile("cp.async.cg.shared.global [%0], [%1], 16;" \
                 :: "r"(dst), "l"(src) : "memory")
#define CP_COMMIT() asm volatile("cp.async.commit_group;" ::: "memory")
#define CP_WAIT2()  asm volatile("cp.async.wait_group 2;" ::: "memory")
#define LDM_X4(r0, r1, r2, r3, addr) \
    asm volatile("ldmatrix.sync.aligned.m8n8.x4.shared.b16 {%0,%1,%2,%3}, [%4];" \
                 : "=r"(r0), "=r"(r1), "=r"(r2), "=r"(r3) : "r"(addr))
#define MMA16816(c, a, b) \
    asm volatile("mma.sync.aligned.m16n8k16.row.col.f32.bf16.bf16.f32 " \
                 "{%0,%1,%2,%3}, {%4,%5,%6,%7}, {%8,%9}, {%0,%1,%2,%3};" \
                 : "+f"((c)[0]), "+f"((c)[1]), "+f"((c)[2]), "+f"((c)[3]) \
                 : "r"((a)[0]), "r"((a)[1]), "r"((a)[2]), "r"((a)[3]), \
                   "r"((b)[0]), "r"((b)[1]))

// ---------------------------------------------------------------------------
// RoPE table + apply
// ---------------------------------------------------------------------------
__global__ void rope_table_kernel()
{
    int idx = blockIdx.x * blockDim.x + threadIdx.x;
    if (idx >= SEQ * 32) return;
    int p = idx & 31;
    int s = idx >> 5;
    double inv = pow(10000.0, -(double)p / 32.0);
    double sd, cd;
    sincos((double)s * inv, &sd, &cd);
    g_cos[idx] = (float)cd;
    g_sin[idx] = (float)sd;
}

__global__ void rope_apply_kernel()
{
    int t = blockIdx.x * blockDim.x + threadIdx.x;
    if (t >= BATCH * NH * SEQ * 8) return;
    int pq = t & 7;
    int s = (t >> 3) & (SEQ - 1);
    int bh = t >> 14;
    float4 c = *(const float4*)&g_cos[s * 32 + pq * 4];
    float4 sn = *(const float4*)&g_sin[s * 32 + pq * 4];
    size_t base = ((size_t)bh * SEQ + s) * DH + pq * 4;

    float4 q1 = *(const float4*)&g_Q[base];
    float4 q2 = *(const float4*)&g_Q[base + 32];
    float4 r1, r2;
    r1.x = q1.x * c.x - q2.x * sn.x;  r2.x = q2.x * c.x + q1.x * sn.x;
    r1.y = q1.y * c.y - q2.y * sn.y;  r2.y = q2.y * c.y + q1.y * sn.y;
    r1.z = q1.z * c.z - q2.z * sn.z;  r2.z = q2.z * c.z + q1.z * sn.z;
    r1.w = q1.w * c.w - q2.w * sn.w;  r2.w = q2.w * c.w + q1.w * sn.w;
    *(float4*)&g_Q[base] = r1;
    *(float4*)&g_Q[base + 32] = r2;

    float4 k1 = *(const float4*)&g_K[base];
    float4 k2 = *(const float4*)&g_K[base + 32];
    r1.x = k1.x * c.x - k2.x * sn.x;  r2.x = k2.x * c.x + k1.x * sn.x;
    r1.y = k1.y * c.y - k2.y * sn.y;  r2.y = k2.y * c.y + k1.y * sn.y;
    r1.z = k1.z * c.z - k2.z * sn.z;  r2.z = k2.z * c.z + k1.z * sn.z;
    r1.w = k1.w * c.w - k2.w * sn.w;  r2.w = k2.w * c.w + k1.w * sn.w;
    *(float4*)&g_K[base] = r1;
    *(float4*)&g_K[base + 32] = r2;
}

// ---------------------------------------------------------------------------
// fp32 -> (hi,lo) bf16 split
// ---------------------------------------------------------------------------
__global__ void split_kernel(const float* __restrict__ src,
                             __nv_bfloat16* __restrict__ dst, int n4)
{
    int i = blockIdx.x * blockDim.x + threadIdx.x;
    if (i >= n4) return;
    int row = i >> 8;
    int kq = (i & 255) << 2;
    float4 v = *(const float4*)&src[(size_t)row * 1024 + kq];
    __nv_bfloat16 h0 = __float2bfloat16(v.x);
    __nv_bfloat16 h1 = __float2bfloat16(v.y);
    __nv_bfloat16 h2 = __float2bfloat16(v.z);
    __nv_bfloat16 h3 = __float2bfloat16(v.w);
    __nv_bfloat16 l0 = __float2bfloat16(v.x - __bfloat162float(h0));
    __nv_bfloat16 l1 = __float2bfloat16(v.y - __bfloat162float(h1));
    __nv_bfloat16 l2 = __float2bfloat16(v.z - __bfloat162float(h2));
    __nv_bfloat16 l3 = __float2bfloat16(v.w - __bfloat162float(h3));
    ushort4 hp, lp;
    hp.x = *(unsigned short*)&h0; hp.y = *(unsigned short*)&h1;
    hp.z = *(unsigned short*)&h2; hp.w = *(unsigned short*)&h3;
    lp.x = *(unsigned short*)&l0; lp.y = *(unsigned short*)&l1;
    lp.z = *(unsigned short*)&l2; lp.w = *(unsigned short*)&l3;
    size_t rb = (size_t)row * 2048;
    *(ushort4*)&dst[rb + kq] = hp;
    *(ushort4*)&dst[rb + 1024 + kq] = lp;
}

// ---------------------------------------------------------------------------
// HMMA bf16x3 GEMM: Y[M,1024] = A[M,1024] @ W^T (fp32 exactness via split).
// A cat [M,2048] bf16, W cat [1024,2048] bf16. Effective K = 3072 (3 terms).
// CTA: 128x128 tile, 256 thr = 8 warps (2m x 4n), warp = 64x32.
// Smem rows padded to 80B; 3-stage cp.async pipeline, K-chunk = 32 bf16.
// QKV=1: grid (32, 24); by/8 selects W & Y, by%8 = n-block; head layout out.
// QKV=0: grid (32, 8); row-major out.
// ---------------------------------------------------------------------------
#define ROWB 80                   // bytes per smem row (32 bf16 + pad)
#define STAGE (128*ROWB)          // per-operand stage bytes (10240)
#define NCHUNK 96

template<int QKV>
__global__ __launch_bounds__(256)
void hmma_gemm(const __nv_bfloat16* __restrict__ A,
               const __nv_bfloat16* __restrict__ W0,
               const __nv_bfloat16* __restrict__ W1,
               const __nv_bfloat16* __restrict__ W2,
               float* __restrict__ Y0, float* __restrict__ Y1,
               float* __restrict__ Y2)
{
    extern __shared__ char smem[];
    const uint32_t sb = smem_u32(smem);
    // layout: [stage][A(10240) | W(10240)] x3
    const int tid = threadIdx.x;
    const int lane = tid & 31;
    const int w = tid >> 5;
    const int wm = w & 1, wn = w >> 1;

    const int m0 = blockIdx.x * 128;
    const int by = blockIdx.y;
    const int ws = QKV ? (by >> 3) : 0;
    const int nblk = by & 7;

    const __nv_bfloat16* W = W0;
    float* Y = Y0;
    if (QKV) {
        if (ws == 1) { W = W1; Y = Y1; }
        else if (ws == 2) { W = W2; Y = Y2; }
    }

    // loader coords: thread t -> row t>>1, quarters (t&1)*2 + {0,1}
    const int lrow = tid >> 1;
    const int lq = (tid & 1) * 2;
    const __nv_bfloat16* Asrc = A + (size_t)(m0 + lrow) * 2048 + lq * 8;
    const __nv_bfloat16* Wsrc = W + (size_t)(nblk * 128 + lrow) * 2048 + lq * 8;
    const uint32_t dstA = sb + lrow * ROWB + lq * 16;
    const uint32_t dstW = dstA + STAGE;

    float c[4][4][4];
#pragma unroll
    for (int i = 0; i < 4; i++)
#pragma unroll
        for (int j = 0; j < 4; j++)
#pragma unroll
            for (int q = 0; q < 4; q++) c[i][j][q] = 0.f;

    // chunk -> k offsets: t = c/32 (0:hi*whi 1:hi*wlo 2:lo*whi), kc = c%32
#define CHUNK_KA(cc) ((((cc) >> 5) == 2 ? 1024 : 0) + ((cc) & 31) * 32)
#define CHUNK_KW(cc) ((((cc) >> 5) == 1 ? 1024 : 0) + ((cc) & 31) * 32)

    // prologue: stages 0..2 <- chunks 0..2
#pragma unroll
    for (int s = 0; s < 3; s++) {
        int kA = CHUNK_KA(s), kW = CHUNK_KW(s);
        uint32_t so = s * 2 * STAGE;
        CP_ASYNC16(dstA + so,      Asrc + kA);
        CP_ASYNC16(dstA + so + 16, Asrc + kA + 8);
        CP_ASYNC16(dstW + so,      Wsrc + kW);
        CP_ASYNC16(dstW + so + 16, Wsrc + kW + 8);
        CP_COMMIT();
    }

    // ldmatrix lane addressing (within stage)
    const uint32_t aLd = sb + (wm * 64 + (lane & 15)) * ROWB + (lane >> 4) * 16;
    const uint32_t bLd = sb + STAGE +
        (wn * 32 + (lane & 7) + ((lane >> 4) & 1) * 8) * ROWB + ((lane >> 3) & 1) * 16;

    int stage = 0;
    for (int cc = 0; cc < NCHUNK; cc++) {
        CP_WAIT2();
        __syncthreads();
        const uint32_t so = stage * 2 * STAGE;
#pragma unroll
        for (int kh = 0; kh < 2; kh++) {
            uint32_t a[4][4], b[4][2];
#pragma unroll
            for (int mt = 0; mt < 4; mt++)
                LDM_X4(a[mt][0], a[mt][1], a[mt][2], a[mt][3],
                       aLd + so + mt * 16 * ROWB + kh * 32);
#pragma unroll
            for (int p = 0; p < 2; p++)
                LDM_X4(b[2*p][0], b[2*p][1], b[2*p+1][0], b[2*p+1][1],
                       bLd + so + p * 16 * ROWB + kh * 32);
#pragma unroll
            for (int mt = 0; mt < 4; mt++)
#pragma unroll
                for (int nt = 0; nt < 4; nt++)
                    MMA16816(c[mt][nt], a[mt], b[nt]);
        }
        __syncthreads();
        if (cc + 3 < NCHUNK) {
            int kA = CHUNK_KA(cc + 3), kW = CHUNK_KW(cc + 3);
            CP_ASYNC16(dstA + so,      Asrc + kA);
            CP_ASYNC16(dstA + so + 16, Asrc + kA + 8);
            CP_ASYNC16(dstW + so,      Wsrc + kW);
            CP_ASYNC16(dstW + so + 16, Wsrc + kW + 8);
        }
        CP_COMMIT();
        stage = (stage == 2) ? 0 : stage + 1;
    }

    // Epilogue
#pragma unroll
    for (int mt = 0; mt < 4; mt++) {
        int mrow = m0 + wm * 64 + mt * 16 + (lane >> 2);
#pragma unroll
        for (int nt = 0; nt < 4; nt++) {
            int n = nblk * 128 + wn * 32 + nt * 8 + (lane & 3) * 2;
            if (QKV) {
                int h = n >> 6, d0 = n & 63;
                int b = mrow >> 11, s = mrow & (SEQ - 1);
                float* dst = Y + (((size_t)((b << 4) + h) * SEQ + s) * DH + d0);
                *(float2*)dst = make_float2(c[mt][nt][0], c[mt][nt][1]);
                *(float2*)(dst + 8 * DH) = make_float2(c[mt][nt][2], c[mt][nt][3]);
            } else {
                float* dst = Y + (size_t)mrow * 1024 + n;
                *(float2*)dst = make_float2(c[mt][nt][0], c[mt][nt][1]);
                *(float2*)(dst + 8 * 1024) = make_float2(c[mt][nt][2], c[mt][nt][3]);
            }
        }
    }
}

// ---------------------------------------------------------------------------
// Flash attention (causal), unchanged from R2.
// ---------------------------------------------------------------------------
__global__ __launch_bounds__(256)
void attn_kernel()
{
    extern __shared__ float sm[];
    float* Qs = sm;
    float* Ks = Qs + 64 * 132;
    float* Vs = Ks + 64 * 68;
    float* Ps = Vs + 64 * 64;

    const int qt = blockIdx.x;
    const int bh = blockIdx.y;
    const int q0 = qt * 128;
    const int b = bh >> 4, h = bh & 15;
    const float* Qg = g_Q + ((size_t)bh * SEQ + q0) * DH;
    const float* Kg = g_K + (size_t)bh * SEQ * DH;
    const float* Vg = g_V + (size_t)bh * SEQ * DH;

    const int tid = threadIdx.x;
    const int tx = tid & 15, ty = tid >> 4;

#pragma unroll
    for (int i = 0; i < 8; i++) {
        int f = tid + i * 256;
        int r = f >> 4;
        int d = (f & 15) << 2;
        float4 v = *(const float4*)&Qg[r * DH + d];
        Qs[(d + 0) * 132 + r] = v.x;
        Qs[(d + 1) * 132 + r] = v.y;
        Qs[(d + 2) * 132 + r] = v.z;
        Qs[(d + 3) * 132 + r] = v.w;
    }

    float m_i[8], l_i[8], o[8][4];
#pragma unroll
    for (int i = 0; i < 8; i++) {
        m_i[i] = -1e30f; l_i[i] = 0.f;
#pragma unroll
        for (int c = 0; c < 4; c++) o[i][c] = 0.f;
    }

    const int nt = qt * 2 + 2;
    for (int t = 0; t < nt; t++) {
        const int j0 = t * 64;
#pragma unroll
        for (int i = 0; i < 4; i++) {
            int f = tid + i * 256;
            int r = f >> 4;
            int d = (f & 15) << 2;
            float4 kv = *(const float4*)&Kg[(size_t)(j0 + r) * DH + d];
            Ks[(d + 0) * 68 + r] = kv.x;
            Ks[(d + 1) * 68 + r] = kv.y;
            Ks[(d + 2) * 68 + r] = kv.z;
            Ks[(d + 3) * 68 + r] = kv.w;
            float4 vv = *(const float4*)&Vg[(size_t)(j0 + r) * DH + d];
            *(float4*)&Vs[r * DH + d] = vv;
        }
        __syncthreads();

        float sacc[8][4];
#pragma unroll
        for (int i = 0; i < 8; i++)
#pragma unroll
            for (int c = 0; c < 4; c++) sacc[i][c] = 0.f;

#pragma unroll 8
        for (int d = 0; d < 64; d++) {
            float4 qa = *(const float4*)&Qs[d * 132 + ty * 8];
            float4 qb = *(const float4*)&Qs[d * 132 + ty * 8 + 4];
            float4 kv = *(const float4*)&Ks[d * 68 + tx * 4];
            float av[8] = {qa.x, qa.y, qa.z, qa.w, qb.x, qb.y, qb.z, qb.w};
            float bv[4] = {kv.x, kv.y, kv.z, kv.w};
#pragma unroll
            for (int i = 0; i < 8; i++)
#pragma unroll
                for (int c = 0; c < 4; c++)
                    sacc[i][c] = fmaf(av[i], bv[c], sacc[i][c]);
        }

#pragma unroll
        for (int i = 0; i < 8; i++) {
            const int row = q0 + ty * 8 + i;
            float sv[4];
#pragma unroll
            for (int c = 0; c < 4; c++) {
                int col = j0 + tx * 4 + c;
                sv[c] = (col <= row) ? sacc[i][c] * 0.125f : -1e30f;
            }
            float mx = fmaxf(fmaxf(sv[0], sv[1]), fmaxf(sv[2], sv[3]));
            mx = fmaxf(mx, __shfl_xor_sync(0xffffffffu, mx, 1));
            mx = fmaxf(mx, __shfl_xor_sync(0xffffffffu, mx, 2));
            mx = fmaxf(mx, __shfl_xor_sync(0xffffffffu, mx, 4));
            mx = fmaxf(mx, __shfl_xor_sync(0xffffffffu, mx, 8));
            float mnew = fmaxf(m_i[i], mx);
            float alpha = __expf(m_i[i] - mnew);
            m_i[i] = mnew;
            float p0 = __expf(sv[0] - mnew);
            float p1 = __expf(sv[1] - mnew);
            float p2 = __expf(sv[2] - mnew);
            float p3 = __expf(sv[3] - mnew);
            float rs = p0 + p1 + p2 + p3;
            rs += __shfl_xor_sync(0xffffffffu, rs, 1);
            rs += __shfl_xor_sync(0xffffffffu, rs, 2);
            rs += __shfl_xor_sync(0xffffffffu, rs, 4);
            rs += __shfl_xor_sync(0xffffffffu, rs, 8);
            l_i[i] = l_i[i] * alpha + rs;
#pragma unroll
            for (int c = 0; c < 4; c++) o[i][c] *= alpha;
            Ps[(tx * 4 + 0) * 132 + ty * 8 + i] = p0;
            Ps[(tx * 4 + 1) * 132 + ty * 8 + i] = p1;
            Ps[(tx * 4 + 2) * 132 + ty * 8 + i] = p2;
            Ps[(tx * 4 + 3) * 132 + ty * 8 + i] = p3;
        }
        __syncthreads();

#pragma unroll 8
        for (int k = 0; k < 64; k++) {
            float4 pa = *(const float4*)&Ps[k * 132 + ty * 8];
            float4 pb = *(const float4*)&Ps[k * 132 + ty * 8 + 4];
            float4 vv = *(const float4*)&Vs[k * DH + tx * 4];
            float pv[8] = {pa.x, pa.y, pa.z, pa.w, pb.x, pb.y, pb.z, pb.w};
#pragma unroll
            for (int i = 0; i < 8; i++) {
                o[i][0] = fmaf(pv[i], vv.x, o[i][0]);
                o[i][1] = fmaf(pv[i], vv.y, o[i][1]);
                o[i][2] = fmaf(pv[i], vv.z, o[i][2]);
                o[i][3] = fmaf(pv[i], vv.w, o[i][3]);
            }
        }
        __syncthreads();
    }

#pragma unroll
    for (int i = 0; i < 8; i++) {
        float invl = 1.f / l_i[i];
        int srow = q0 + ty * 8 + i;
        float4 v = make_float4(o[i][0] * invl, o[i][1] * invl,
                               o[i][2] * invl, o[i][3] * invl);
        *(float4*)&g_att[((size_t)b * SEQ + srow) * DMODEL + h * DH + tx * 4] = v;
    }
}

// ---------------------------------------------------------------------------
// Launch
// ---------------------------------------------------------------------------
extern "C" void kernel_launch(void* const* d_in, const int* in_sizes, int n_in,
                              void* d_out, int out_size)
{
    const float* x  = (const float*)d_in[0];
    const float* Wq = (const float*)d_in[2];
    const float* Wk = (const float*)d_in[3];
    const float* Wv = (const float*)d_in[4];
    const float* Wo = (const float*)d_in[5];
    float* out = (float*)d_out;

    float *qp, *kp, *vp, *ap;
    cudaGetSymbolAddress((void**)&qp, g_Q);
    cudaGetSymbolAddress((void**)&kp, g_K);
    cudaGetSymbolAddress((void**)&vp, g_V);
    cudaGetSymbolAddress((void**)&ap, g_att);
    void *xc, *ac, *wqc, *wkc, *wvc, *woc;
    cudaGetSymbolAddress(&xc, g_Xcat);
    cudaGetSymbolAddress(&ac, g_Acat);
    cudaGetSymbolAddress(&wqc, g_Wqc);
    cudaGetSymbolAddress(&wkc, g_Wkc);
    cudaGetSymbolAddress(&wvc, g_Wvc);
    cudaGetSymbolAddress(&woc, g_Woc);

    rope_table_kernel<<<(SEQ * 32 + 255) / 256, 256>>>();

    split_kernel<<<(MTOT * 256 + 255) / 256, 256>>>(x, (__nv_bfloat16*)xc, MTOT * 256);
    split_kernel<<<(1024 * 256 + 255) / 256, 256>>>(Wq, (__nv_bfloat16*)wqc, 1024 * 256);
    split_kernel<<<(1024 * 256 + 255) / 256, 256>>>(Wk, (__nv_bfloat16*)wkc, 1024 * 256);
    split_kernel<<<(1024 * 256 + 255) / 256, 256>>>(Wv, (__nv_bfloat16*)wvc, 1024 * 256);
    split_kernel<<<(1024 * 256 + 255) / 256, 256>>>(Wo, (__nv_bfloat16*)woc, 1024 * 256);

    const int gsmem = 3 * 2 * STAGE;   // 61440
    cudaFuncSetAttribute(hmma_gemm<1>, cudaFuncAttributeMaxDynamicSharedMemorySize, gsmem);
    cudaFuncSetAttribute(hmma_gemm<0>, cudaFuncAttributeMaxDynamicSharedMemorySize, gsmem);

    hmma_gemm<1><<<dim3(MTOT / 128, 24), 256, gsmem>>>(
        (const __nv_bfloat16*)xc, (const __nv_bfloat16*)wqc,
        (const __nv_bfloat16*)wkc, (const __nv_bfloat16*)wvc, qp, kp, vp);

    rope_apply_kernel<<<(BATCH * NH * SEQ * 8 + 255) / 256, 256>>>();

    int smem = 64 * (132 + 68 + 64 + 132) * (int)sizeof(float);
    cudaFuncSetAttribute(attn_kernel, cudaFuncAttributeMaxDynamicSharedMemorySize, smem);
    attn_kernel<<<dim3(SEQ / 128, BATCH * NH), 256, smem>>>();

    split_kernel<<<(MTOT * 256 + 255) / 256, 256>>>(ap, (__nv_bfloat16*)ac, MTOT * 256);

    hmma_gemm<0><<<dim3(MTOT / 128, 8), 256, gsmem>>>(
        (const __nv_bfloat16*)ac, (const __nv_bfloat16*)woc,
        nullptr, nullptr, out, nullptr, nullptr);
}

// round 6
// speedup vs baseline: 2.6954x; 1.6295x over previous
#include <cuda_runtime.h>
#include <cuda_bf16.h>
#include <math.h>
#include <stdint.h>

#define BATCH 2
#define SEQ 2048
#define DMODEL 1024
#define NH 16
#define DH 64
#define MTOT (BATCH*SEQ)
#define BH (BATCH*NH)

// ---------------------------------------------------------------------------
// Device global scratch
// ---------------------------------------------------------------------------
__device__ __align__(128) float g_Q[BH*SEQ*DH];
__device__ __align__(128) float g_K[BH*SEQ*DH];
__device__ __align__(128) float g_V[BH*SEQ*DH];
__device__ __align__(128) float g_att[(size_t)MTOT*DMODEL];
__device__ float g_cos[SEQ*32];
__device__ float g_sin[SEQ*32];
// bf16 split buffers for projections: [rows][2048] (hi | lo)
__device__ __align__(128) __nv_bfloat16 g_Xcat[(size_t)MTOT*2048];
__device__ __align__(128) __nv_bfloat16 g_Acat[(size_t)MTOT*2048];
__device__ __align__(128) __nv_bfloat16 g_Wqc[1024*2048];
__device__ __align__(128) __nv_bfloat16 g_Wkc[1024*2048];
__device__ __align__(128) __nv_bfloat16 g_Wvc[1024*2048];
__device__ __align__(128) __nv_bfloat16 g_Woc[1024*2048];
// bf16 split attention operands: [bh*S][128] = (hi 64 | lo 64)
__device__ __align__(128) __nv_bfloat16 g_Qc[(size_t)BH*SEQ*128];
__device__ __align__(128) __nv_bfloat16 g_Kc[(size_t)BH*SEQ*128];
__device__ __align__(128) __nv_bfloat16 g_Vc[(size_t)BH*SEQ*128];

__device__ __forceinline__ uint32_t smem_u32(const void* p) {
    uint32_t a;
    asm("{ .reg .u64 t; cvta.to.shared.u64 t, %1; cvt.u32.u64 %0, t; }"
        : "=r"(a) : "l"(p));
    return a;
}
#define CP_ASYNC16(dst, src) \
    asm volatile("cp.async.cg.shared.global [%0], [%1], 16;" \
                 :: "r"(dst), "l"(src) : "memory")
#define CP_COMMIT() asm volatile("cp.async.commit_group;" ::: "memory")
#define CP_WAIT2()  asm volatile("cp.async.wait_group 2;" ::: "memory")
#define CP_WAIT1()  asm volatile("cp.async.wait_group 1;" ::: "memory")
#define LDM_X4(r0, r1, r2, r3, addr) \
    asm volatile("ldmatrix.sync.aligned.m8n8.x4.shared.b16 {%0,%1,%2,%3}, [%4];" \
                 : "=r"(r0), "=r"(r1), "=r"(r2), "=r"(r3) : "r"(addr))
#define LDM_X4_T(r0, r1, r2, r3, addr) \
    asm volatile("ldmatrix.sync.aligned.m8n8.x4.trans.shared.b16 {%0,%1,%2,%3}, [%4];" \
                 : "=r"(r0), "=r"(r1), "=r"(r2), "=r"(r3) : "r"(addr))
#define MMA16816(c, a, b) \
    asm volatile("mma.sync.aligned.m16n8k16.row.col.f32.bf16.bf16.f32 " \
                 "{%0,%1,%2,%3}, {%4,%5,%6,%7}, {%8,%9}, {%0,%1,%2,%3};" \
                 : "+f"((c)[0]), "+f"((c)[1]), "+f"((c)[2]), "+f"((c)[3]) \
                 : "r"((a)[0]), "r"((a)[1]), "r"((a)[2]), "r"((a)[3]), \
                   "r"((b)[0]), "r"((b)[1]))

__device__ __forceinline__ uint32_t packbf(float lo, float hi) {
    uint32_t r;
    asm("cvt.rn.bf16x2.f32 %0, %2, %1;" : "=r"(r) : "f"(lo), "f"(hi));
    return r;
}

// ---------------------------------------------------------------------------
// RoPE table
// ---------------------------------------------------------------------------
__global__ void rope_table_kernel()
{
    int idx = blockIdx.x * blockDim.x + threadIdx.x;
    if (idx >= SEQ * 32) return;
    int p = idx & 31;
    int s = idx >> 5;
    double inv = pow(10000.0, -(double)p / 32.0);
    double sd, cd;
    sincos((double)s * inv, &sd, &cd);
    g_cos[idx] = (float)cd;
    g_sin[idx] = (float)sd;
}

// ---------------------------------------------------------------------------
// RoPE apply + bf16 hi/lo split
// ---------------------------------------------------------------------------
__global__ void rope_split_kernel()
{
    int t = blockIdx.x * blockDim.x + threadIdx.x;
    if (t >= BH * SEQ * 8) return;
    int pq = t & 7;
    int s = (t >> 3) & (SEQ - 1);
    int bh = t >> 14;
    float4 c = *(const float4*)&g_cos[s * 32 + pq * 4];
    float4 sn = *(const float4*)&g_sin[s * 32 + pq * 4];
    size_t base = ((size_t)bh * SEQ + s) * DH + pq * 4;
    size_t cbase = ((size_t)bh * SEQ + s) * 128 + pq * 4;

#pragma unroll
    for (int which = 0; which < 2; which++) {
        const float* src = which ? g_K : g_Q;
        __nv_bfloat16* dst = which ? g_Kc : g_Qc;
        float4 a1 = *(const float4*)&src[base];
        float4 a2 = *(const float4*)&src[base + 32];
        float r1[4], r2[4];
        r1[0] = a1.x * c.x - a2.x * sn.x;  r2[0] = a2.x * c.x + a1.x * sn.x;
        r1[1] = a1.y * c.y - a2.y * sn.y;  r2[1] = a2.y * c.y + a1.y * sn.y;
        r1[2] = a1.z * c.z - a2.z * sn.z;  r2[2] = a2.z * c.z + a1.z * sn.z;
        r1[3] = a1.w * c.w - a2.w * sn.w;  r2[3] = a2.w * c.w + a1.w * sn.w;
        ushort4 h1, h2, l1, l2;
        unsigned short* hp1 = (unsigned short*)&h1;
        unsigned short* hp2 = (unsigned short*)&h2;
        unsigned short* lp1 = (unsigned short*)&l1;
        unsigned short* lp2 = (unsigned short*)&l2;
#pragma unroll
        for (int i = 0; i < 4; i++) {
            __nv_bfloat16 h = __float2bfloat16(r1[i]);
            hp1[i] = *(unsigned short*)&h;
            __nv_bfloat16 l = __float2bfloat16(r1[i] - __bfloat162float(h));
            lp1[i] = *(unsigned short*)&l;
            h = __float2bfloat16(r2[i]);
            hp2[i] = *(unsigned short*)&h;
            l = __float2bfloat16(r2[i] - __bfloat162float(h));
            lp2[i] = *(unsigned short*)&l;
        }
        *(ushort4*)&dst[cbase] = h1;
        *(ushort4*)&dst[cbase + 32] = h2;
        *(ushort4*)&dst[cbase + 64] = l1;
        *(ushort4*)&dst[cbase + 96] = l2;
    }
}

// ---------------------------------------------------------------------------
// V split
// ---------------------------------------------------------------------------
__global__ void vsplit_kernel()
{
    int t = blockIdx.x * blockDim.x + threadIdx.x;
    if (t >= BH * SEQ * 8) return;
    int pq = t & 7;
    int row = t >> 3;
    const float* src = g_V + (size_t)row * 64 + pq * 8;
    float4 a = *(const float4*)src;
    float4 b = *(const float4*)(src + 4);
    float v[8] = {a.x, a.y, a.z, a.w, b.x, b.y, b.z, b.w};
    ushort4 h[2], l[2];
    unsigned short* hp = (unsigned short*)h;
    unsigned short* lp = (unsigned short*)l;
#pragma unroll
    for (int i = 0; i < 8; i++) {
        __nv_bfloat16 hh = __float2bfloat16(v[i]);
        hp[i] = *(unsigned short*)&hh;
        __nv_bfloat16 ll = __float2bfloat16(v[i] - __bfloat162float(hh));
        lp[i] = *(unsigned short*)&ll;
    }
    __nv_bfloat16* dst = g_Vc + (size_t)row * 128;
    *(uint4*)&dst[pq * 8] = *(uint4*)h;
    *(uint4*)&dst[64 + pq * 8] = *(uint4*)l;
}

// ---------------------------------------------------------------------------
// fp32 -> (hi,lo) bf16 split for projection operands
// ---------------------------------------------------------------------------
__global__ void split_kernel(const float* __restrict__ src,
                             __nv_bfloat16* __restrict__ dst, int n4)
{
    int i = blockIdx.x * blockDim.x + threadIdx.x;
    if (i >= n4) return;
    int row = i >> 8;
    int kq = (i & 255) << 2;
    float4 v = *(const float4*)&src[(size_t)row * 1024 + kq];
    __nv_bfloat16 h0 = __float2bfloat16(v.x);
    __nv_bfloat16 h1 = __float2bfloat16(v.y);
    __nv_bfloat16 h2 = __float2bfloat16(v.z);
    __nv_bfloat16 h3 = __float2bfloat16(v.w);
    __nv_bfloat16 l0 = __float2bfloat16(v.x - __bfloat162float(h0));
    __nv_bfloat16 l1 = __float2bfloat16(v.y - __bfloat162float(h1));
    __nv_bfloat16 l2 = __float2bfloat16(v.z - __bfloat162float(h2));
    __nv_bfloat16 l3 = __float2bfloat16(v.w - __bfloat162float(h3));
    ushort4 hp, lp;
    hp.x = *(unsigned short*)&h0; hp.y = *(unsigned short*)&h1;
    hp.z = *(unsigned short*)&h2; hp.w = *(unsigned short*)&h3;
    lp.x = *(unsigned short*)&l0; lp.y = *(unsigned short*)&l1;
    lp.z = *(unsigned short*)&l2; lp.w = *(unsigned short*)&l3;
    size_t rb = (size_t)row * 2048;
    *(ushort4*)&dst[rb + kq] = hp;
    *(ushort4*)&dst[rb + 1024 + kq] = lp;
}

// ---------------------------------------------------------------------------
// HMMA bf16x3 projection GEMM (unchanged from R4)
// ---------------------------------------------------------------------------
#define ROWB 80
#define STAGE (128*ROWB)
#define NCHUNK 96

template<int QKV>
__global__ __launch_bounds__(256)
void hmma_gemm(const __nv_bfloat16* __restrict__ A,
               const __nv_bfloat16* __restrict__ W0,
               const __nv_bfloat16* __restrict__ W1,
               const __nv_bfloat16* __restrict__ W2,
               float* __restrict__ Y0, float* __restrict__ Y1,
               float* __restrict__ Y2)
{
    extern __shared__ char smem[];
    const uint32_t sb = smem_u32(smem);
    const int tid = threadIdx.x;
    const int lane = tid & 31;
    const int w = tid >> 5;
    const int wm = w & 1, wn = w >> 1;

    const int m0 = blockIdx.x * 128;
    const int by = blockIdx.y;
    const int ws = QKV ? (by >> 3) : 0;
    const int nblk = by & 7;

    const __nv_bfloat16* W = W0;
    float* Y = Y0;
    if (QKV) {
        if (ws == 1) { W = W1; Y = Y1; }
        else if (ws == 2) { W = W2; Y = Y2; }
    }

    const int lrow = tid >> 1;
    const int lq = (tid & 1) * 2;
    const __nv_bfloat16* Asrc = A + (size_t)(m0 + lrow) * 2048 + lq * 8;
    const __nv_bfloat16* Wsrc = W + (size_t)(nblk * 128 + lrow) * 2048 + lq * 8;
    const uint32_t dstA = sb + lrow * ROWB + lq * 16;
    const uint32_t dstW = dstA + STAGE;

    float c[4][4][4];
#pragma unroll
    for (int i = 0; i < 4; i++)
#pragma unroll
        for (int j = 0; j < 4; j++)
#pragma unroll
            for (int q = 0; q < 4; q++) c[i][j][q] = 0.f;

#define CHUNK_KA(cc) ((((cc) >> 5) == 2 ? 1024 : 0) + ((cc) & 31) * 32)
#define CHUNK_KW(cc) ((((cc) >> 5) == 1 ? 1024 : 0) + ((cc) & 31) * 32)

#pragma unroll
    for (int s = 0; s < 3; s++) {
        int kA = CHUNK_KA(s), kW = CHUNK_KW(s);
        uint32_t so = s * 2 * STAGE;
        CP_ASYNC16(dstA + so,      Asrc + kA);
        CP_ASYNC16(dstA + so + 16, Asrc + kA + 8);
        CP_ASYNC16(dstW + so,      Wsrc + kW);
        CP_ASYNC16(dstW + so + 16, Wsrc + kW + 8);
        CP_COMMIT();
    }

    const uint32_t aLd = sb + (wm * 64 + (lane & 15)) * ROWB + (lane >> 4) * 16;
    const uint32_t bLd = sb + STAGE +
        (wn * 32 + (lane & 7) + ((lane >> 4) & 1) * 8) * ROWB + ((lane >> 3) & 1) * 16;

    int stage = 0;
    for (int cc = 0; cc < NCHUNK; cc++) {
        CP_WAIT2();
        __syncthreads();
        const uint32_t so = stage * 2 * STAGE;
#pragma unroll
        for (int kh = 0; kh < 2; kh++) {
            uint32_t a[4][4], b[4][2];
#pragma unroll
            for (int mt = 0; mt < 4; mt++)
                LDM_X4(a[mt][0], a[mt][1], a[mt][2], a[mt][3],
                       aLd + so + mt * 16 * ROWB + kh * 32);
#pragma unroll
            for (int p = 0; p < 2; p++)
                LDM_X4(b[2*p][0], b[2*p][1], b[2*p+1][0], b[2*p+1][1],
                       bLd + so + p * 16 * ROWB + kh * 32);
#pragma unroll
            for (int mt = 0; mt < 4; mt++)
#pragma unroll
                for (int nt = 0; nt < 4; nt++)
                    MMA16816(c[mt][nt], a[mt], b[nt]);
        }
        __syncthreads();
        if (cc + 3 < NCHUNK) {
            int kA = CHUNK_KA(cc + 3), kW = CHUNK_KW(cc + 3);
            CP_ASYNC16(dstA + so,      Asrc + kA);
            CP_ASYNC16(dstA + so + 16, Asrc + kA + 8);
            CP_ASYNC16(dstW + so,      Wsrc + kW);
            CP_ASYNC16(dstW + so + 16, Wsrc + kW + 8);
        }
        CP_COMMIT();
        stage = (stage == 2) ? 0 : stage + 1;
    }

#pragma unroll
    for (int mt = 0; mt < 4; mt++) {
        int mrow = m0 + wm * 64 + mt * 16 + (lane >> 2);
#pragma unroll
        for (int nt = 0; nt < 4; nt++) {
            int n = nblk * 128 + wn * 32 + nt * 8 + (lane & 3) * 2;
            if (QKV) {
                int h = n >> 6, d0 = n & 63;
                int b = mrow >> 11, s = mrow & (SEQ - 1);
                float* dst = Y + (((size_t)((b << 4) + h) * SEQ + s) * DH + d0);
                *(float2*)dst = make_float2(c[mt][nt][0], c[mt][nt][1]);
                *(float2*)(dst + 8 * DH) = make_float2(c[mt][nt][2], c[mt][nt][3]);
            } else {
                float* dst = Y + (size_t)mrow * 1024 + n;
                *(float2*)dst = make_float2(c[mt][nt][0], c[mt][nt][1]);
                *(float2*)(dst + 8 * 1024) = make_float2(c[mt][nt][2], c[mt][nt][3]);
            }
        }
    }
}

// ---------------------------------------------------------------------------
// Tensor-core flash attention (causal). FIXED causal-mask skip condition.
// ---------------------------------------------------------------------------
#define AROWB 272
#define QBYTES (128*AROWB)
#define KVBYTES (64*AROWB)
#define ASTAGE (2*KVBYTES)
#define ATT_SMEM (QBYTES + 2*ASTAGE)

__global__ __launch_bounds__(256)
void attn_mma_kernel()
{
    extern __shared__ char smem[];
    const uint32_t sb = smem_u32(smem);
    const uint32_t Qs = sb;
    const uint32_t St0 = sb + QBYTES;

    const int qt = blockIdx.x;
    const int bh = blockIdx.y;
    const int q0 = qt * 128;
    const int b = bh >> 4, h = bh & 15;

    const int tid = threadIdx.x;
    const int lane = tid & 31;
    const int w = tid >> 5;

    const char* Qg = (const char*)(g_Qc + ((size_t)bh * SEQ + q0) * 128);
    const char* Kg = (const char*)(g_Kc + (size_t)bh * SEQ * 128);
    const char* Vg = (const char*)(g_Vc + (size_t)bh * SEQ * 128);

#pragma unroll
    for (int i = 0; i < 8; i++) {
        int idx = tid + i * 256;
        int r = idx >> 4, ch = (idx & 15) * 16;
        CP_ASYNC16(Qs + r * AROWB + ch, Qg + r * 256 + ch);
    }
#pragma unroll
    for (int i = 0; i < 8; i++) {
        int idx = tid + i * 256;
        if (idx < 1024) {
            int r = idx >> 4, ch = (idx & 15) * 16;
            CP_ASYNC16(St0 + r * AROWB + ch, Kg + r * 256 + ch);
        } else {
            int j = idx - 1024;
            int r = j >> 4, ch = (j & 15) * 16;
            CP_ASYNC16(St0 + KVBYTES + r * AROWB + ch, Vg + r * 256 + ch);
        }
    }
    CP_COMMIT();

    float of[8][4];
#pragma unroll
    for (int i = 0; i < 8; i++)
#pragma unroll
        for (int q = 0; q < 4; q++) of[i][q] = 0.f;
    float m0r = -1e30f, m1r = -1e30f, l0r = 0.f, l1r = 0.f;
    uint32_t qh[4][4], ql[4][4];

    const uint32_t qLd = Qs + (w * 16 + (lane & 15)) * AROWB + (lane >> 4) * 16;
    const uint32_t kRow = ((lane >> 4) & 1) * 8 + (lane & 7);
    const uint32_t kCol = ((lane >> 3) & 1) * 16;
    const uint32_t vRow = ((lane >> 3) & 1) * 8 + (lane & 7);
    const uint32_t vCol = ((lane >> 4) & 1) * 16;

    const int g = lane >> 2;
    const int cq = (lane & 3) * 2;
    const int wrow = q0 + w * 16;          // warp's min row
    const int row0 = wrow + g;
    const int row1 = row0 + 8;

    const int nt = qt * 2 + 2;
    for (int t = 0; t < nt; t++) {
        if (t + 1 < nt) {
            const uint32_t stN = St0 + ((t + 1) & 1) * ASTAGE;
            const char* Kn = Kg + (size_t)(t + 1) * 64 * 256;
            const char* Vn = Vg + (size_t)(t + 1) * 64 * 256;
#pragma unroll
            for (int i = 0; i < 8; i++) {
                int idx = tid + i * 256;
                if (idx < 1024) {
                    int r = idx >> 4, ch = (idx & 15) * 16;
                    CP_ASYNC16(stN + r * AROWB + ch, Kn + r * 256 + ch);
                } else {
                    int j = idx - 1024;
                    int r = j >> 4, ch = (j & 15) * 16;
                    CP_ASYNC16(stN + KVBYTES + r * AROWB + ch, Vn + r * 256 + ch);
                }
            }
        }
        CP_COMMIT();
        CP_WAIT1();
        __syncthreads();

        if (t == 0) {
#pragma unroll
            for (int ks = 0; ks < 4; ks++) {
                LDM_X4(qh[ks][0], qh[ks][1], qh[ks][2], qh[ks][3], qLd + ks * 32);
                LDM_X4(ql[ks][0], ql[ks][1], ql[ks][2], ql[ks][3], qLd + 128 + ks * 32);
            }
        }

        const int j0 = t * 64;
        // Warp-level skip: tile entirely above this warp's rows -> all masked.
        if (j0 <= wrow + 15) {
            const uint32_t stK = St0 + (t & 1) * ASTAGE;
            const uint32_t stV = stK + KVBYTES;
            const uint32_t kLd = stK + kRow * AROWB + kCol;
            const uint32_t vLd = stV + vRow * AROWB + vCol;

            float sc[8][4];
#pragma unroll
            for (int i = 0; i < 8; i++)
#pragma unroll
                for (int q = 0; q < 4; q++) sc[i][q] = 0.f;

#pragma unroll
            for (int ks = 0; ks < 4; ks++) {
                uint32_t bh_[8][2], bl_[8][2];
#pragma unroll
                for (int p = 0; p < 4; p++) {
                    LDM_X4(bh_[2*p][0], bh_[2*p][1], bh_[2*p+1][0], bh_[2*p+1][1],
                           kLd + p * 16 * AROWB + ks * 32);
                    LDM_X4(bl_[2*p][0], bl_[2*p][1], bl_[2*p+1][0], bl_[2*p+1][1],
                           kLd + p * 16 * AROWB + 128 + ks * 32);
                }
#pragma unroll
                for (int nb = 0; nb < 8; nb++) {
                    MMA16816(sc[nb], qh[ks], bh_[nb]);
                    MMA16816(sc[nb], ql[ks], bh_[nb]);
                    MMA16816(sc[nb], qh[ks], bl_[nb]);
                }
            }

            // FIXED: compare against warp's MIN row
            const bool domask = (j0 + 63 > wrow);
#pragma unroll
            for (int nb = 0; nb < 8; nb++) {
                int col = j0 + nb * 8 + cq;
#pragma unroll
                for (int q = 0; q < 4; q++) sc[nb][q] *= 0.125f;
                if (domask) {
                    if (col     > row0) sc[nb][0] = -1e30f;
                    if (col + 1 > row0) sc[nb][1] = -1e30f;
                    if (col     > row1) sc[nb][2] = -1e30f;
                    if (col + 1 > row1) sc[nb][3] = -1e30f;
                }
            }

            float mx0 = -1e30f, mx1 = -1e30f;
#pragma unroll
            for (int nb = 0; nb < 8; nb++) {
                mx0 = fmaxf(mx0, fmaxf(sc[nb][0], sc[nb][1]));
                mx1 = fmaxf(mx1, fmaxf(sc[nb][2], sc[nb][3]));
            }
            mx0 = fmaxf(mx0, __shfl_xor_sync(0xffffffffu, mx0, 1));
            mx0 = fmaxf(mx0, __shfl_xor_sync(0xffffffffu, mx0, 2));
            mx1 = fmaxf(mx1, __shfl_xor_sync(0xffffffffu, mx1, 1));
            mx1 = fmaxf(mx1, __shfl_xor_sync(0xffffffffu, mx1, 2));

            float mn0 = fmaxf(m0r, mx0), mn1 = fmaxf(m1r, mx1);
            float al0 = __expf(m0r - mn0), al1 = __expf(m1r - mn1);
            m0r = mn0; m1r = mn1;

            float rs0 = 0.f, rs1 = 0.f;
#pragma unroll
            for (int nb = 0; nb < 8; nb++) {
                sc[nb][0] = __expf(sc[nb][0] - mn0);
                sc[nb][1] = __expf(sc[nb][1] - mn0);
                sc[nb][2] = __expf(sc[nb][2] - mn1);
                sc[nb][3] = __expf(sc[nb][3] - mn1);
                rs0 += sc[nb][0] + sc[nb][1];
                rs1 += sc[nb][2] + sc[nb][3];
            }
            rs0 += __shfl_xor_sync(0xffffffffu, rs0, 1);
            rs0 += __shfl_xor_sync(0xffffffffu, rs0, 2);
            rs1 += __shfl_xor_sync(0xffffffffu, rs1, 1);
            rs1 += __shfl_xor_sync(0xffffffffu, rs1, 2);
            l0r = l0r * al0 + rs0;
            l1r = l1r * al1 + rs1;

#pragma unroll
            for (int i = 0; i < 8; i++) {
                of[i][0] *= al0; of[i][1] *= al0;
                of[i][2] *= al1; of[i][3] *= al1;
            }

#pragma unroll
            for (int ks = 0; ks < 4; ks++) {
                uint32_t aPh[4], aPl[4];
                float* s0 = sc[2 * ks];
                float* s1 = sc[2 * ks + 1];
                aPh[0] = packbf(s0[0], s0[1]);
                aPh[1] = packbf(s0[2], s0[3]);
                aPh[2] = packbf(s1[0], s1[1]);
                aPh[3] = packbf(s1[2], s1[3]);
#pragma unroll
                for (int q = 0; q < 4; q++) {
                    float* sp = (q < 2) ? s0 : s1;
                    int o2 = (q & 1) * 2;
                    float h0 = __uint_as_float(aPh[q] << 16);
                    float h1 = __uint_as_float(aPh[q] & 0xffff0000u);
                    aPl[q] = packbf(sp[o2] - h0, sp[o2 + 1] - h1);
                }
                uint32_t vh[4], vl[4];
#pragma unroll
                for (int p = 0; p < 4; p++) {
                    LDM_X4_T(vh[0], vh[1], vh[2], vh[3],
                             vLd + ks * 16 * AROWB + p * 32);
                    LDM_X4_T(vl[0], vl[1], vl[2], vl[3],
                             vLd + ks * 16 * AROWB + 128 + p * 32);
                    MMA16816(of[2*p],     aPh, vh);
                    MMA16816(of[2*p + 1], aPh, vh + 2);
                    MMA16816(of[2*p],     aPl, vh);
                    MMA16816(of[2*p + 1], aPl, vh + 2);
                    MMA16816(of[2*p],     aPh, vl);
                    MMA16816(of[2*p + 1], aPh, vl + 2);
                }
            }
        }
        __syncthreads();
    }

    float inv0 = 1.f / l0r, inv1 = 1.f / l1r;
    float* outb = g_att + ((size_t)b * SEQ) * DMODEL + h * DH;
#pragma unroll
    for (int nb = 0; nb < 8; nb++) {
        int d = nb * 8 + cq;
        *(float2*)(outb + (size_t)row0 * DMODEL + d) =
            make_float2(of[nb][0] * inv0, of[nb][1] * inv0);
        *(float2*)(outb + (size_t)row1 * DMODEL + d) =
            make_float2(of[nb][2] * inv1, of[nb][3] * inv1);
    }
}

// ---------------------------------------------------------------------------
// Launch
// ---------------------------------------------------------------------------
extern "C" void kernel_launch(void* const* d_in, const int* in_sizes, int n_in,
                              void* d_out, int out_size)
{
    const float* x  = (const float*)d_in[0];
    const float* Wq = (const float*)d_in[2];
    const float* Wk = (const float*)d_in[3];
    const float* Wv = (const float*)d_in[4];
    const float* Wo = (const float*)d_in[5];
    float* out = (float*)d_out;

    float *qp, *kp, *vp, *ap;
    cudaGetSymbolAddress((void**)&qp, g_Q);
    cudaGetSymbolAddress((void**)&kp, g_K);
    cudaGetSymbolAddress((void**)&vp, g_V);
    cudaGetSymbolAddress((void**)&ap, g_att);
    void *xc, *ac, *wqc, *wkc, *wvc, *woc;
    cudaGetSymbolAddress(&xc, g_Xcat);
    cudaGetSymbolAddress(&ac, g_Acat);
    cudaGetSymbolAddress(&wqc, g_Wqc);
    cudaGetSymbolAddress(&wkc, g_Wkc);
    cudaGetSymbolAddress(&wvc, g_Wvc);
    cudaGetSymbolAddress(&woc, g_Woc);

    rope_table_kernel<<<(SEQ * 32 + 255) / 256, 256>>>();

    split_kernel<<<(MTOT * 256 + 255) / 256, 256>>>(x, (__nv_bfloat16*)xc, MTOT * 256);
    split_kernel<<<(1024 * 256 + 255) / 256, 256>>>(Wq, (__nv_bfloat16*)wqc, 1024 * 256);
    split_kernel<<<(1024 * 256 + 255) / 256, 256>>>(Wk, (__nv_bfloat16*)wkc, 1024 * 256);
    split_kernel<<<(1024 * 256 + 255) / 256, 256>>>(Wv, (__nv_bfloat16*)wvc, 1024 * 256);
    split_kernel<<<(1024 * 256 + 255) / 256, 256>>>(Wo, (__nv_bfloat16*)woc, 1024 * 256);

    const int gsmem = 3 * 2 * STAGE;
    cudaFuncSetAttribute(hmma_gemm<1>, cudaFuncAttributeMaxDynamicSharedMemorySize, gsmem);
    cudaFuncSetAttribute(hmma_gemm<0>, cudaFuncAttributeMaxDynamicSharedMemorySize, gsmem);

    hmma_gemm<1><<<dim3(MTOT / 128, 24), 256, gsmem>>>(
        (const __nv_bfloat16*)xc, (const __nv_bfloat16*)wqc,
        (const __nv_bfloat16*)wkc, (const __nv_bfloat16*)wvc, qp, kp, vp);

    int nth = BH * SEQ * 8;
    rope_split_kernel<<<(nth + 255) / 256, 256>>>();
    vsplit_kernel<<<(nth + 255) / 256, 256>>>();

    cudaFuncSetAttribute(attn_mma_kernel,
                         cudaFuncAttributeMaxDynamicSharedMemorySize, ATT_SMEM);
    attn_mma_kernel<<<dim3(SEQ / 128, BH), 256, ATT_SMEM>>>();

    split_kernel<<<(MTOT * 256 + 255) / 256, 256>>>(ap, (__nv_bfloat16*)ac, MTOT * 256);

    hmma_gemm<0><<<dim3(MTOT / 128, 8), 256, gsmem>>>(
        (const __nv_bfloat16*)ac, (const __nv_bfloat16*)woc,
        nullptr, nullptr, out, nullptr, nullptr);
}

// round 7
// speedup vs baseline: 2.7583x; 1.0233x over previous
#include <cuda_runtime.h>
#include <cuda_bf16.h>
#include <math.h>
#include <stdint.h>

#define BATCH 2
#define SEQ 2048
#define DMODEL 1024
#define NH 16
#define DH 64
#define MTOT (BATCH*SEQ)
#define BH (BATCH*NH)

// ---------------------------------------------------------------------------
// Device global scratch
// ---------------------------------------------------------------------------
__device__ __align__(128) float g_Q[BH*SEQ*DH];
__device__ __align__(128) float g_K[BH*SEQ*DH];
__device__ float g_cos[SEQ*32];
__device__ float g_sin[SEQ*32];
// bf16 split buffers for projections: [rows][2048] (hi | lo)
__device__ __align__(128) __nv_bfloat16 g_Xcat[(size_t)MTOT*2048];
__device__ __align__(128) __nv_bfloat16 g_Acat[(size_t)MTOT*2048];
__device__ __align__(128) __nv_bfloat16 g_Wqc[1024*2048];
__device__ __align__(128) __nv_bfloat16 g_Wkc[1024*2048];
__device__ __align__(128) __nv_bfloat16 g_Wvc[1024*2048];
__device__ __align__(128) __nv_bfloat16 g_Woc[1024*2048];
// bf16 split attention operands: [bh*S][128] = (hi 64 | lo 64)
__device__ __align__(128) __nv_bfloat16 g_Qc[(size_t)BH*SEQ*128];
__device__ __align__(128) __nv_bfloat16 g_Kc[(size_t)BH*SEQ*128];
__device__ __align__(128) __nv_bfloat16 g_Vc[(size_t)BH*SEQ*128];

__device__ __forceinline__ uint32_t smem_u32(const void* p) {
    uint32_t a;
    asm("{ .reg .u64 t; cvta.to.shared.u64 t, %1; cvt.u32.u64 %0, t; }"
        : "=r"(a) : "l"(p));
    return a;
}
#define CP_ASYNC16(dst, src) \
    asm volatile("cp.async.cg.shared.global [%0], [%1], 16;" \
                 :: "r"(dst), "l"(src) : "memory")
#define CP_COMMIT() asm volatile("cp.async.commit_group;" ::: "memory")
#define CP_WAIT1()  asm volatile("cp.async.wait_group 1;" ::: "memory")
#define LDM_X4(r0, r1, r2, r3, addr) \
    asm volatile("ldmatrix.sync.aligned.m8n8.x4.shared.b16 {%0,%1,%2,%3}, [%4];" \
                 : "=r"(r0), "=r"(r1), "=r"(r2), "=r"(r3) : "r"(addr))
#define LDM_X4_T(r0, r1, r2, r3, addr) \
    asm volatile("ldmatrix.sync.aligned.m8n8.x4.trans.shared.b16 {%0,%1,%2,%3}, [%4];" \
                 : "=r"(r0), "=r"(r1), "=r"(r2), "=r"(r3) : "r"(addr))
#define MMA16816(c, a, b) \
    asm volatile("mma.sync.aligned.m16n8k16.row.col.f32.bf16.bf16.f32 " \
                 "{%0,%1,%2,%3}, {%4,%5,%6,%7}, {%8,%9}, {%0,%1,%2,%3};" \
                 : "+f"((c)[0]), "+f"((c)[1]), "+f"((c)[2]), "+f"((c)[3]) \
                 : "r"((a)[0]), "r"((a)[1]), "r"((a)[2]), "r"((a)[3]), \
                   "r"((b)[0]), "r"((b)[1]))

__device__ __forceinline__ uint32_t packbf(float lo, float hi) {
    uint32_t r;
    asm("cvt.rn.bf16x2.f32 %0, %2, %1;" : "=r"(r) : "f"(lo), "f"(hi));
    return r;
}

// ---------------------------------------------------------------------------
// RoPE table
// ---------------------------------------------------------------------------
__global__ void rope_table_kernel()
{
    int idx = blockIdx.x * blockDim.x + threadIdx.x;
    if (idx >= SEQ * 32) return;
    int p = idx & 31;
    int s = idx >> 5;
    double inv = pow(10000.0, -(double)p / 32.0);
    double sd, cd;
    sincos((double)s * inv, &sd, &cd);
    g_cos[idx] = (float)cd;
    g_sin[idx] = (float)sd;
}

// ---------------------------------------------------------------------------
// RoPE apply + bf16 hi/lo split
// ---------------------------------------------------------------------------
__global__ void rope_split_kernel()
{
    int t = blockIdx.x * blockDim.x + threadIdx.x;
    if (t >= BH * SEQ * 8) return;
    int pq = t & 7;
    int s = (t >> 3) & (SEQ - 1);
    int bh = t >> 14;
    float4 c = *(const float4*)&g_cos[s * 32 + pq * 4];
    float4 sn = *(const float4*)&g_sin[s * 32 + pq * 4];
    size_t base = ((size_t)bh * SEQ + s) * DH + pq * 4;
    size_t cbase = ((size_t)bh * SEQ + s) * 128 + pq * 4;

#pragma unroll
    for (int which = 0; which < 2; which++) {
        const float* src = which ? g_K : g_Q;
        __nv_bfloat16* dst = which ? g_Kc : g_Qc;
        float4 a1 = *(const float4*)&src[base];
        float4 a2 = *(const float4*)&src[base + 32];
        float r1[4], r2[4];
        r1[0] = a1.x * c.x - a2.x * sn.x;  r2[0] = a2.x * c.x + a1.x * sn.x;
        r1[1] = a1.y * c.y - a2.y * sn.y;  r2[1] = a2.y * c.y + a1.y * sn.y;
        r1[2] = a1.z * c.z - a2.z * sn.z;  r2[2] = a2.z * c.z + a1.z * sn.z;
        r1[3] = a1.w * c.w - a2.w * sn.w;  r2[3] = a2.w * c.w + a1.w * sn.w;
        ushort4 h1, h2, l1, l2;
        unsigned short* hp1 = (unsigned short*)&h1;
        unsigned short* hp2 = (unsigned short*)&h2;
        unsigned short* lp1 = (unsigned short*)&l1;
        unsigned short* lp2 = (unsigned short*)&l2;
#pragma unroll
        for (int i = 0; i < 4; i++) {
            __nv_bfloat16 h = __float2bfloat16(r1[i]);
            hp1[i] = *(unsigned short*)&h;
            __nv_bfloat16 l = __float2bfloat16(r1[i] - __bfloat162float(h));
            lp1[i] = *(unsigned short*)&l;
            h = __float2bfloat16(r2[i]);
            hp2[i] = *(unsigned short*)&h;
            l = __float2bfloat16(r2[i] - __bfloat162float(h));
            lp2[i] = *(unsigned short*)&l;
        }
        *(ushort4*)&dst[cbase] = h1;
        *(ushort4*)&dst[cbase + 32] = h2;
        *(ushort4*)&dst[cbase + 64] = l1;
        *(ushort4*)&dst[cbase + 96] = l2;
    }
}

// ---------------------------------------------------------------------------
// fp32 -> (hi,lo) bf16 split for projection operands
// ---------------------------------------------------------------------------
__global__ void split_kernel(const float* __restrict__ src,
                             __nv_bfloat16* __restrict__ dst, int n4)
{
    int i = blockIdx.x * blockDim.x + threadIdx.x;
    if (i >= n4) return;
    int row = i >> 8;
    int kq = (i & 255) << 2;
    float4 v = *(const float4*)&src[(size_t)row * 1024 + kq];
    __nv_bfloat16 h0 = __float2bfloat16(v.x);
    __nv_bfloat16 h1 = __float2bfloat16(v.y);
    __nv_bfloat16 h2 = __float2bfloat16(v.z);
    __nv_bfloat16 h3 = __float2bfloat16(v.w);
    __nv_bfloat16 l0 = __float2bfloat16(v.x - __bfloat162float(h0));
    __nv_bfloat16 l1 = __float2bfloat16(v.y - __bfloat162float(h1));
    __nv_bfloat16 l2 = __float2bfloat16(v.z - __bfloat162float(h2));
    __nv_bfloat16 l3 = __float2bfloat16(v.w - __bfloat162float(h3));
    ushort4 hp, lp;
    hp.x = *(unsigned short*)&h0; hp.y = *(unsigned short*)&h1;
    hp.z = *(unsigned short*)&h2; hp.w = *(unsigned short*)&h3;
    lp.x = *(unsigned short*)&l0; lp.y = *(unsigned short*)&l1;
    lp.z = *(unsigned short*)&l2; lp.w = *(unsigned short*)&l3;
    size_t rb = (size_t)row * 2048;
    *(ushort4*)&dst[rb + kq] = hp;
    *(ushort4*)&dst[rb + 1024 + kq] = lp;
}

// ---------------------------------------------------------------------------
// HMMA bf16x3 projection GEMM, K-chunk 64, 3 stages, single sync/iter.
// QKV=1: blockIdx.y: ws=by/8 selects Wq/Wk/Wv; V (ws==2) written as bf16
//        hi/lo direct to g_Vc; Q/K written fp32 head layout.
// QKV=0: row-major fp32 out.
// ---------------------------------------------------------------------------
#define ROWB2 144                  // 128B data + 16B pad
#define OPST (128*ROWB2)           // 18432 per operand per stage
#define STG2 (2*OPST)              // 36864 per stage
#define GSMEM (3*STG2)             // 110592
#define NCH2 48

template<int QKV>
__global__ __launch_bounds__(256, 2)
void hmma_gemm(const __nv_bfloat16* __restrict__ A,
               const __nv_bfloat16* __restrict__ W0,
               const __nv_bfloat16* __restrict__ W1,
               const __nv_bfloat16* __restrict__ W2,
               float* __restrict__ Y0, float* __restrict__ Y1,
               float* __restrict__ Y2)
{
    extern __shared__ char smem[];
    const uint32_t sb = smem_u32(smem);
    const int tid = threadIdx.x;
    const int lane = tid & 31;
    const int w = tid >> 5;
    const int wm = w & 1, wn = w >> 1;

    const int m0 = blockIdx.x * 128;
    const int by = blockIdx.y;
    const int ws = QKV ? (by >> 3) : 0;
    const int nblk = by & 7;

    const __nv_bfloat16* W = W0;
    float* Y = Y0;
    if (QKV) {
        if (ws == 1) { W = W1; Y = Y1; }
        else if (ws == 2) { W = W2; Y = Y2; }
    }

    // loader: thread t -> row t>>1, half (t&1): 64B = 4 x 16B per operand
    const int lrow = tid >> 1;
    const int lhalf = (tid & 1) * 32;     // element offset within 64-el chunk
    const __nv_bfloat16* Asrc = A + (size_t)(m0 + lrow) * 2048 + lhalf;
    const __nv_bfloat16* Wsrc = W + (size_t)(nblk * 128 + lrow) * 2048 + lhalf;
    const uint32_t dstA = sb + lrow * ROWB2 + lhalf * 2;
    const uint32_t dstW = dstA + OPST;

    float c[4][4][4];
#pragma unroll
    for (int i = 0; i < 4; i++)
#pragma unroll
        for (int j = 0; j < 4; j++)
#pragma unroll
            for (int q = 0; q < 4; q++) c[i][j][q] = 0.f;

    // chunk cc (0..47): term t = cc/16, kc = cc%16
#define C2_KA(cc) ((((cc) >> 4) == 2 ? 1024 : 0) + ((cc) & 15) * 64)
#define C2_KW(cc) ((((cc) >> 4) == 1 ? 1024 : 0) + ((cc) & 15) * 64)

    // prologue: chunks 0,1 -> stages 0,1
#pragma unroll
    for (int s = 0; s < 2; s++) {
        int kA = C2_KA(s), kW = C2_KW(s);
        uint32_t so = s * STG2;
#pragma unroll
        for (int q = 0; q < 4; q++) {
            CP_ASYNC16(dstA + so + q * 16, Asrc + kA + q * 8);
            CP_ASYNC16(dstW + so + q * 16, Wsrc + kW + q * 8);
        }
        CP_COMMIT();
    }

    const uint32_t aLd = sb + (wm * 64 + (lane & 15)) * ROWB2 + (lane >> 4) * 16;
    const uint32_t bLd = sb + OPST +
        (wn * 32 + (lane & 7) + ((lane >> 4) & 1) * 8) * ROWB2 + ((lane >> 3) & 1) * 16;

    int stage = 0;
    for (int cc = 0; cc < NCH2; cc++) {
        CP_WAIT1();
        __syncthreads();
        // prefetch chunk cc+2 into stage (cc+2)%3 (consumed at iter cc-1)
        if (cc + 2 < NCH2) {
            int sn = stage + 2; if (sn >= 3) sn -= 3;
            int kA = C2_KA(cc + 2), kW = C2_KW(cc + 2);
            uint32_t so = sn * STG2;
#pragma unroll
            for (int q = 0; q < 4; q++) {
                CP_ASYNC16(dstA + so + q * 16, Asrc + kA + q * 8);
                CP_ASYNC16(dstW + so + q * 16, Wsrc + kW + q * 8);
            }
        }
        CP_COMMIT();

        const uint32_t so = stage * STG2;
#pragma unroll
        for (int kh = 0; kh < 4; kh++) {
            uint32_t a[4][4], b[4][2];
#pragma unroll
            for (int mt = 0; mt < 4; mt++)
                LDM_X4(a[mt][0], a[mt][1], a[mt][2], a[mt][3],
                       aLd + so + mt * 16 * ROWB2 + kh * 32);
#pragma unroll
            for (int p = 0; p < 2; p++)
                LDM_X4(b[2*p][0], b[2*p][1], b[2*p+1][0], b[2*p+1][1],
                       bLd + so + p * 16 * ROWB2 + kh * 32);
#pragma unroll
            for (int mt = 0; mt < 4; mt++)
#pragma unroll
                for (int nt = 0; nt < 4; nt++)
                    MMA16816(c[mt][nt], a[mt], b[nt]);
        }
        stage = (stage == 2) ? 0 : stage + 1;
    }

#pragma unroll
    for (int mt = 0; mt < 4; mt++) {
        int mrow = m0 + wm * 64 + mt * 16 + (lane >> 2);
#pragma unroll
        for (int nt = 0; nt < 4; nt++) {
            int n = nblk * 128 + wn * 32 + nt * 8 + (lane & 3) * 2;
            if (QKV) {
                int h = n >> 6, d0 = n & 63;
                int b = mrow >> 11, s = mrow & (SEQ - 1);
                if (ws == 2) {
                    // V: write bf16 hi/lo direct to g_Vc layout via Y(=g_Vc)
                    __nv_bfloat16* dst = (__nv_bfloat16*)Y +
                        (((size_t)((b << 4) + h) * SEQ + s) * 128 + d0);
                    uint32_t hp0 = packbf(c[mt][nt][0], c[mt][nt][1]);
                    float f0 = __uint_as_float(hp0 << 16);
                    float f1 = __uint_as_float(hp0 & 0xffff0000u);
                    uint32_t lp0 = packbf(c[mt][nt][0] - f0, c[mt][nt][1] - f1);
                    *(uint32_t*)dst = hp0;
                    *(uint32_t*)(dst + 64) = lp0;
                    uint32_t hp1 = packbf(c[mt][nt][2], c[mt][nt][3]);
                    float f2 = __uint_as_float(hp1 << 16);
                    float f3 = __uint_as_float(hp1 & 0xffff0000u);
                    uint32_t lp1 = packbf(c[mt][nt][2] - f2, c[mt][nt][3] - f3);
                    *(uint32_t*)(dst + 8 * 128) = hp1;
                    *(uint32_t*)(dst + 8 * 128 + 64) = lp1;
                } else {
                    float* dst = Y + (((size_t)((b << 4) + h) * SEQ + s) * DH + d0);
                    *(float2*)dst = make_float2(c[mt][nt][0], c[mt][nt][1]);
                    *(float2*)(dst + 8 * DH) = make_float2(c[mt][nt][2], c[mt][nt][3]);
                }
            } else {
                float* dst = Y + (size_t)mrow * 1024 + n;
                *(float2*)dst = make_float2(c[mt][nt][0], c[mt][nt][1]);
                *(float2*)(dst + 8 * 1024) = make_float2(c[mt][nt][2], c[mt][nt][3]);
            }
        }
    }
}

// ---------------------------------------------------------------------------
// Tensor-core flash attention (causal). Epilogue writes bf16 hi/lo to g_Acat.
// ---------------------------------------------------------------------------
#define AROWB 272
#define QBYTES (128*AROWB)
#define KVBYTES (64*AROWB)
#define ASTAGE (2*KVBYTES)
#define ATT_SMEM (QBYTES + 2*ASTAGE)

__global__ __launch_bounds__(256)
void attn_mma_kernel()
{
    extern __shared__ char smem[];
    const uint32_t sb = smem_u32(smem);
    const uint32_t Qs = sb;
    const uint32_t St0 = sb + QBYTES;

    const int qt = blockIdx.x;
    const int bh = blockIdx.y;
    const int q0 = qt * 128;
    const int b = bh >> 4, h = bh & 15;

    const int tid = threadIdx.x;
    const int lane = tid & 31;
    const int w = tid >> 5;

    const char* Qg = (const char*)(g_Qc + ((size_t)bh * SEQ + q0) * 128);
    const char* Kg = (const char*)(g_Kc + (size_t)bh * SEQ * 128);
    const char* Vg = (const char*)(g_Vc + (size_t)bh * SEQ * 128);

#pragma unroll
    for (int i = 0; i < 8; i++) {
        int idx = tid + i * 256;
        int r = idx >> 4, ch = (idx & 15) * 16;
        CP_ASYNC16(Qs + r * AROWB + ch, Qg + r * 256 + ch);
    }
#pragma unroll
    for (int i = 0; i < 8; i++) {
        int idx = tid + i * 256;
        if (idx < 1024) {
            int r = idx >> 4, ch = (idx & 15) * 16;
            CP_ASYNC16(St0 + r * AROWB + ch, Kg + r * 256 + ch);
        } else {
            int j = idx - 1024;
            int r = j >> 4, ch = (j & 15) * 16;
            CP_ASYNC16(St0 + KVBYTES + r * AROWB + ch, Vg + r * 256 + ch);
        }
    }
    CP_COMMIT();

    float of[8][4];
#pragma unroll
    for (int i = 0; i < 8; i++)
#pragma unroll
        for (int q = 0; q < 4; q++) of[i][q] = 0.f;
    float m0r = -1e30f, m1r = -1e30f, l0r = 0.f, l1r = 0.f;
    uint32_t qh[4][4], ql[4][4];

    const uint32_t qLd = Qs + (w * 16 + (lane & 15)) * AROWB + (lane >> 4) * 16;
    const uint32_t kRow = ((lane >> 4) & 1) * 8 + (lane & 7);
    const uint32_t kCol = ((lane >> 3) & 1) * 16;
    const uint32_t vRow = ((lane >> 3) & 1) * 8 + (lane & 7);
    const uint32_t vCol = ((lane >> 4) & 1) * 16;

    const int g = lane >> 2;
    const int cq = (lane & 3) * 2;
    const int wrow = q0 + w * 16;
    const int row0 = wrow + g;
    const int row1 = row0 + 8;

    const int nt = qt * 2 + 2;
    for (int t = 0; t < nt; t++) {
        if (t + 1 < nt) {
            const uint32_t stN = St0 + ((t + 1) & 1) * ASTAGE;
            const char* Kn = Kg + (size_t)(t + 1) * 64 * 256;
            const char* Vn = Vg + (size_t)(t + 1) * 64 * 256;
#pragma unroll
            for (int i = 0; i < 8; i++) {
                int idx = tid + i * 256;
                if (idx < 1024) {
                    int r = idx >> 4, ch = (idx & 15) * 16;
                    CP_ASYNC16(stN + r * AROWB + ch, Kn + r * 256 + ch);
                } else {
                    int j = idx - 1024;
                    int r = j >> 4, ch = (j & 15) * 16;
                    CP_ASYNC16(stN + KVBYTES + r * AROWB + ch, Vn + r * 256 + ch);
                }
            }
        }
        CP_COMMIT();
        CP_WAIT1();
        __syncthreads();

        if (t == 0) {
#pragma unroll
            for (int ks = 0; ks < 4; ks++) {
                LDM_X4(qh[ks][0], qh[ks][1], qh[ks][2], qh[ks][3], qLd + ks * 32);
                LDM_X4(ql[ks][0], ql[ks][1], ql[ks][2], ql[ks][3], qLd + 128 + ks * 32);
            }
        }

        const int j0 = t * 64;
        if (j0 <= wrow + 15) {
            const uint32_t stK = St0 + (t & 1) * ASTAGE;
            const uint32_t stV = stK + KVBYTES;
            const uint32_t kLd = stK + kRow * AROWB + kCol;
            const uint32_t vLd = stV + vRow * AROWB + vCol;

            float sc[8][4];
#pragma unroll
            for (int i = 0; i < 8; i++)
#pragma unroll
                for (int q = 0; q < 4; q++) sc[i][q] = 0.f;

#pragma unroll
            for (int ks = 0; ks < 4; ks++) {
                uint32_t bh_[8][2], bl_[8][2];
#pragma unroll
                for (int p = 0; p < 4; p++) {
                    LDM_X4(bh_[2*p][0], bh_[2*p][1], bh_[2*p+1][0], bh_[2*p+1][1],
                           kLd + p * 16 * AROWB + ks * 32);
                    LDM_X4(bl_[2*p][0], bl_[2*p][1], bl_[2*p+1][0], bl_[2*p+1][1],
                           kLd + p * 16 * AROWB + 128 + ks * 32);
                }
#pragma unroll
                for (int nb = 0; nb < 8; nb++) {
                    MMA16816(sc[nb], qh[ks], bh_[nb]);
                    MMA16816(sc[nb], ql[ks], bh_[nb]);
                    MMA16816(sc[nb], qh[ks], bl_[nb]);
                }
            }

            const bool domask = (j0 + 63 > wrow);
#pragma unroll
            for (int nb = 0; nb < 8; nb++) {
                int col = j0 + nb * 8 + cq;
#pragma unroll
                for (int q = 0; q < 4; q++) sc[nb][q] *= 0.125f;
                if (domask) {
                    if (col     > row0) sc[nb][0] = -1e30f;
                    if (col + 1 > row0) sc[nb][1] = -1e30f;
                    if (col     > row1) sc[nb][2] = -1e30f;
                    if (col + 1 > row1) sc[nb][3] = -1e30f;
                }
            }

            float mx0 = -1e30f, mx1 = -1e30f;
#pragma unroll
            for (int nb = 0; nb < 8; nb++) {
                mx0 = fmaxf(mx0, fmaxf(sc[nb][0], sc[nb][1]));
                mx1 = fmaxf(mx1, fmaxf(sc[nb][2], sc[nb][3]));
            }
            mx0 = fmaxf(mx0, __shfl_xor_sync(0xffffffffu, mx0, 1));
            mx0 = fmaxf(mx0, __shfl_xor_sync(0xffffffffu, mx0, 2));
            mx1 = fmaxf(mx1, __shfl_xor_sync(0xffffffffu, mx1, 1));
            mx1 = fmaxf(mx1, __shfl_xor_sync(0xffffffffu, mx1, 2));

            float mn0 = fmaxf(m0r, mx0), mn1 = fmaxf(m1r, mx1);
            float al0 = __expf(m0r - mn0), al1 = __expf(m1r - mn1);
            m0r = mn0; m1r = mn1;

            float rs0 = 0.f, rs1 = 0.f;
#pragma unroll
            for (int nb = 0; nb < 8; nb++) {
                sc[nb][0] = __expf(sc[nb][0] - mn0);
                sc[nb][1] = __expf(sc[nb][1] - mn0);
                sc[nb][2] = __expf(sc[nb][2] - mn1);
                sc[nb][3] = __expf(sc[nb][3] - mn1);
                rs0 += sc[nb][0] + sc[nb][1];
                rs1 += sc[nb][2] + sc[nb][3];
            }
            rs0 += __shfl_xor_sync(0xffffffffu, rs0, 1);
            rs0 += __shfl_xor_sync(0xffffffffu, rs0, 2);
            rs1 += __shfl_xor_sync(0xffffffffu, rs1, 1);
            rs1 += __shfl_xor_sync(0xffffffffu, rs1, 2);
            l0r = l0r * al0 + rs0;
            l1r = l1r * al1 + rs1;

#pragma unroll
            for (int i = 0; i < 8; i++) {
                of[i][0] *= al0; of[i][1] *= al0;
                of[i][2] *= al1; of[i][3] *= al1;
            }

#pragma unroll
            for (int ks = 0; ks < 4; ks++) {
                uint32_t aPh[4], aPl[4];
                float* s0 = sc[2 * ks];
                float* s1 = sc[2 * ks + 1];
                aPh[0] = packbf(s0[0], s0[1]);
                aPh[1] = packbf(s0[2], s0[3]);
                aPh[2] = packbf(s1[0], s1[1]);
                aPh[3] = packbf(s1[2], s1[3]);
#pragma unroll
                for (int q = 0; q < 4; q++) {
                    float* sp = (q < 2) ? s0 : s1;
                    int o2 = (q & 1) * 2;
                    float h0 = __uint_as_float(aPh[q] << 16);
                    float h1 = __uint_as_float(aPh[q] & 0xffff0000u);
                    aPl[q] = packbf(sp[o2] - h0, sp[o2 + 1] - h1);
                }
                uint32_t vh[4], vl[4];
#pragma unroll
                for (int p = 0; p < 4; p++) {
                    LDM_X4_T(vh[0], vh[1], vh[2], vh[3],
                             vLd + ks * 16 * AROWB + p * 32);
                    LDM_X4_T(vl[0], vl[1], vl[2], vl[3],
                             vLd + ks * 16 * AROWB + 128 + p * 32);
                    MMA16816(of[2*p],     aPh, vh);
                    MMA16816(of[2*p + 1], aPh, vh + 2);
                    MMA16816(of[2*p],     aPl, vh);
                    MMA16816(of[2*p + 1], aPl, vh + 2);
                    MMA16816(of[2*p],     aPh, vl);
                    MMA16816(of[2*p + 1], aPh, vl + 2);
                }
            }
        }
        __syncthreads();
    }

    // epilogue: write bf16 hi/lo direct to g_Acat [token_row][hi1024 | lo1024]
    float inv0 = 1.f / l0r, inv1 = 1.f / l1r;
    __nv_bfloat16* ar0 = g_Acat + ((size_t)(b * SEQ + row0)) * 2048 + h * 64;
    __nv_bfloat16* ar1 = g_Acat + ((size_t)(b * SEQ + row1)) * 2048 + h * 64;
#pragma unroll
    for (int nb = 0; nb < 8; nb++) {
        int d = nb * 8 + cq;
        float v0 = of[nb][0] * inv0, v1 = of[nb][1] * inv0;
        uint32_t hp = packbf(v0, v1);
        float f0 = __uint_as_float(hp << 16);
        float f1 = __uint_as_float(hp & 0xffff0000u);
        uint32_t lp = packbf(v0 - f0, v1 - f1);
        *(uint32_t*)(ar0 + d) = hp;
        *(uint32_t*)(ar0 + 1024 + d) = lp;
        float v2 = of[nb][2] * inv1, v3 = of[nb][3] * inv1;
        uint32_t hp1 = packbf(v2, v3);
        float f2 = __uint_as_float(hp1 << 16);
        float f3 = __uint_as_float(hp1 & 0xffff0000u);
        uint32_t lp1 = packbf(v2 - f2, v3 - f3);
        *(uint32_t*)(ar1 + d) = hp1;
        *(uint32_t*)(ar1 + 1024 + d) = lp1;
    }
}

// ---------------------------------------------------------------------------
// Launch
// ---------------------------------------------------------------------------
extern "C" void kernel_launch(void* const* d_in, const int* in_sizes, int n_in,
                              void* d_out, int out_size)
{
    const float* x  = (const float*)d_in[0];
    const float* Wq = (const float*)d_in[2];
    const float* Wk = (const float*)d_in[3];
    const float* Wv = (const float*)d_in[4];
    const float* Wo = (const float*)d_in[5];
    float* out = (float*)d_out;

    float *qp, *kp;
    cudaGetSymbolAddress((void**)&qp, g_Q);
    cudaGetSymbolAddress((void**)&kp, g_K);
    void *xc, *ac, *wqc, *wkc, *wvc, *woc, *vc;
    cudaGetSymbolAddress(&xc, g_Xcat);
    cudaGetSymbolAddress(&ac, g_Acat);
    cudaGetSymbolAddress(&wqc, g_Wqc);
    cudaGetSymbolAddress(&wkc, g_Wkc);
    cudaGetSymbolAddress(&wvc, g_Wvc);
    cudaGetSymbolAddress(&woc, g_Woc);
    cudaGetSymbolAddress(&vc, g_Vc);

    rope_table_kernel<<<(SEQ * 32 + 255) / 256, 256>>>();

    split_kernel<<<(MTOT * 256 + 255) / 256, 256>>>(x, (__nv_bfloat16*)xc, MTOT * 256);
    split_kernel<<<(1024 * 256 + 255) / 256, 256>>>(Wq, (__nv_bfloat16*)wqc, 1024 * 256);
    split_kernel<<<(1024 * 256 + 255) / 256, 256>>>(Wk, (__nv_bfloat16*)wkc, 1024 * 256);
    split_kernel<<<(1024 * 256 + 255) / 256, 256>>>(Wv, (__nv_bfloat16*)wvc, 1024 * 256);
    split_kernel<<<(1024 * 256 + 255) / 256, 256>>>(Wo, (__nv_bfloat16*)woc, 1024 * 256);

    cudaFuncSetAttribute(hmma_gemm<1>, cudaFuncAttributeMaxDynamicSharedMemorySize, GSMEM);
    cudaFuncSetAttribute(hmma_gemm<0>, cudaFuncAttributeMaxDynamicSharedMemorySize, GSMEM);

    hmma_gemm<1><<<dim3(MTOT / 128, 24), 256, GSMEM>>>(
        (const __nv_bfloat16*)xc, (const __nv_bfloat16*)wqc,
        (const __nv_bfloat16*)wkc, (const __nv_bfloat16*)wvc,
        qp, kp, (float*)vc);

    int nth = BH * SEQ * 8;
    rope_split_kernel<<<(nth + 255) / 256, 256>>>();

    cudaFuncSetAttribute(attn_mma_kernel,
                         cudaFuncAttributeMaxDynamicSharedMemorySize, ATT_SMEM);
    attn_mma_kernel<<<dim3(SEQ / 128, BH), 256, ATT_SMEM>>>();

    hmma_gemm<0><<<dim3(MTOT / 128, 8), 256, GSMEM>>>(
        (const __nv_bfloat16*)ac, (const __nv_bfloat16*)woc,
        nullptr, nullptr, out, nullptr, nullptr);
}

// round 8
// speedup vs baseline: 3.8792x; 1.4064x over previous
#include <cuda_runtime.h>
#include <cuda_fp16.h>
#include <math.h>
#include <stdint.h>

#define BATCH 2
#define SEQ 2048
#define DMODEL 1024
#define NH 16
#define DH 64
#define MTOT (BATCH*SEQ)
#define BH (BATCH*NH)

// ---------------------------------------------------------------------------
// Device global scratch
// ---------------------------------------------------------------------------
__device__ __align__(128) float g_Q[BH*SEQ*DH];
__device__ __align__(128) float g_K[BH*SEQ*DH];
__device__ float g_cos[SEQ*32];
__device__ float g_sin[SEQ*32];
// fp16 split A-operands: [rows][2048] (hi | lo)
__device__ __align__(128) __half g_Xcat[(size_t)MTOT*2048];
__device__ __align__(128) __half g_Acat[(size_t)MTOT*2048];
// fp16 weights (single precision-truncated copy)
__device__ __align__(128) __half g_Wq16[1024*1024];
__device__ __align__(128) __half g_Wk16[1024*1024];
__device__ __align__(128) __half g_Wv16[1024*1024];
__device__ __align__(128) __half g_Wo16[1024*1024];
// attention operands: Q hi/lo [row][128], K/V single fp16 [row][64]
__device__ __align__(128) __half g_Qc[(size_t)BH*SEQ*128];
__device__ __align__(128) __half g_Kc[(size_t)BH*SEQ*64];
__device__ __align__(128) __half g_Vc[(size_t)BH*SEQ*64];

__device__ __forceinline__ uint32_t smem_u32(const void* p) {
    uint32_t a;
    asm("{ .reg .u64 t; cvta.to.shared.u64 t, %1; cvt.u32.u64 %0, t; }"
        : "=r"(a) : "l"(p));
    return a;
}
#define CP_ASYNC16(dst, src) \
    asm volatile("cp.async.cg.shared.global [%0], [%1], 16;" \
                 :: "r"(dst), "l"(src) : "memory")
#define CP_COMMIT() asm volatile("cp.async.commit_group;" ::: "memory")
#define CP_WAIT1()  asm volatile("cp.async.wait_group 1;" ::: "memory")
#define LDM_X4(r0, r1, r2, r3, addr) \
    asm volatile("ldmatrix.sync.aligned.m8n8.x4.shared.b16 {%0,%1,%2,%3}, [%4];" \
                 : "=r"(r0), "=r"(r1), "=r"(r2), "=r"(r3) : "r"(addr))
#define LDM_X4_T(r0, r1, r2, r3, addr) \
    asm volatile("ldmatrix.sync.aligned.m8n8.x4.trans.shared.b16 {%0,%1,%2,%3}, [%4];" \
                 : "=r"(r0), "=r"(r1), "=r"(r2), "=r"(r3) : "r"(addr))
#define MMA16816(c, a, b) \
    asm volatile("mma.sync.aligned.m16n8k16.row.col.f32.f16.f16.f32 " \
                 "{%0,%1,%2,%3}, {%4,%5,%6,%7}, {%8,%9}, {%0,%1,%2,%3};" \
                 : "+f"((c)[0]), "+f"((c)[1]), "+f"((c)[2]), "+f"((c)[3]) \
                 : "r"((a)[0]), "r"((a)[1]), "r"((a)[2]), "r"((a)[3]), \
                   "r"((b)[0]), "r"((b)[1]))

// packs {low=a, high=b}
__device__ __forceinline__ uint32_t packh(float a, float b) {
    uint32_t r;
    asm("cvt.rn.f16x2.f32 %0, %2, %1;" : "=r"(r) : "f"(a), "f"(b));
    return r;
}

// ---------------------------------------------------------------------------
// RoPE table
// ---------------------------------------------------------------------------
__global__ void rope_table_kernel()
{
    int idx = blockIdx.x * blockDim.x + threadIdx.x;
    if (idx >= SEQ * 32) return;
    int p = idx & 31;
    int s = idx >> 5;
    double inv = pow(10000.0, -(double)p / 32.0);
    double sd, cd;
    sincos((double)s * inv, &sd, &cd);
    g_cos[idx] = (float)cd;
    g_sin[idx] = (float)sd;
}

// ---------------------------------------------------------------------------
// RoPE apply: Q -> fp16 hi/lo [row][128]; K -> single fp16 [row][64]
// ---------------------------------------------------------------------------
__global__ void rope_split_kernel()
{
    int t = blockIdx.x * blockDim.x + threadIdx.x;
    if (t >= BH * SEQ * 8) return;
    int pq = t & 7;
    int s = (t >> 3) & (SEQ - 1);
    int bh = t >> 14;
    float4 c = *(const float4*)&g_cos[s * 32 + pq * 4];
    float4 sn = *(const float4*)&g_sin[s * 32 + pq * 4];
    size_t base = ((size_t)bh * SEQ + s) * DH + pq * 4;
    float r1[4], r2[4];

    // Q: hi/lo
    {
        float4 a1 = *(const float4*)&g_Q[base];
        float4 a2 = *(const float4*)&g_Q[base + 32];
        r1[0] = a1.x * c.x - a2.x * sn.x;  r2[0] = a2.x * c.x + a1.x * sn.x;
        r1[1] = a1.y * c.y - a2.y * sn.y;  r2[1] = a2.y * c.y + a1.y * sn.y;
        r1[2] = a1.z * c.z - a2.z * sn.z;  r2[2] = a2.z * c.z + a1.z * sn.z;
        r1[3] = a1.w * c.w - a2.w * sn.w;  r2[3] = a2.w * c.w + a1.w * sn.w;
        ushort4 h1, h2, l1, l2;
        unsigned short *hp1 = (unsigned short*)&h1, *hp2 = (unsigned short*)&h2;
        unsigned short *lp1 = (unsigned short*)&l1, *lp2 = (unsigned short*)&l2;
#pragma unroll
        for (int i = 0; i < 4; i++) {
            __half h = __float2half_rn(r1[i]);
            hp1[i] = *(unsigned short*)&h;
            __half l = __float2half_rn(r1[i] - __half2float(h));
            lp1[i] = *(unsigned short*)&l;
            h = __float2half_rn(r2[i]);
            hp2[i] = *(unsigned short*)&h;
            l = __float2half_rn(r2[i] - __half2float(h));
            lp2[i] = *(unsigned short*)&l;
        }
        __half* qd = g_Qc + ((size_t)bh * SEQ + s) * 128 + pq * 4;
        *(ushort4*)(qd)      = h1;
        *(ushort4*)(qd + 32) = h2;
        *(ushort4*)(qd + 64) = l1;
        *(ushort4*)(qd + 96) = l2;
    }
    // K: single fp16
    {
        float4 a1 = *(const float4*)&g_K[base];
        float4 a2 = *(const float4*)&g_K[base + 32];
        r1[0] = a1.x * c.x - a2.x * sn.x;  r2[0] = a2.x * c.x + a1.x * sn.x;
        r1[1] = a1.y * c.y - a2.y * sn.y;  r2[1] = a2.y * c.y + a1.y * sn.y;
        r1[2] = a1.z * c.z - a2.z * sn.z;  r2[2] = a2.z * c.z + a1.z * sn.z;
        r1[3] = a1.w * c.w - a2.w * sn.w;  r2[3] = a2.w * c.w + a1.w * sn.w;
        ushort4 h1, h2;
        unsigned short *hp1 = (unsigned short*)&h1, *hp2 = (unsigned short*)&h2;
#pragma unroll
        for (int i = 0; i < 4; i++) {
            __half h = __float2half_rn(r1[i]);
            hp1[i] = *(unsigned short*)&h;
            h = __float2half_rn(r2[i]);
            hp2[i] = *(unsigned short*)&h;
        }
        __half* kd = g_Kc + ((size_t)bh * SEQ + s) * 64 + pq * 4;
        *(ushort4*)(kd)      = h1;
        *(ushort4*)(kd + 32) = h2;
    }
}

// ---------------------------------------------------------------------------
// fp32 -> fp16 hi/lo split (for x): dst [row][2048]
// ---------------------------------------------------------------------------
__global__ void split_kernel(const float* __restrict__ src,
                             __half* __restrict__ dst, int n4)
{
    int i = blockIdx.x * blockDim.x + threadIdx.x;
    if (i >= n4) return;
    int row = i >> 8;
    int kq = (i & 255) << 2;
    float4 v = *(const float4*)&src[(size_t)row * 1024 + kq];
    float vv[4] = {v.x, v.y, v.z, v.w};
    ushort4 hp, lp;
    unsigned short* h = (unsigned short*)&hp;
    unsigned short* l = (unsigned short*)&lp;
#pragma unroll
    for (int q = 0; q < 4; q++) {
        __half hh = __float2half_rn(vv[q]);
        h[q] = *(unsigned short*)&hh;
        __half ll = __float2half_rn(vv[q] - __half2float(hh));
        l[q] = *(unsigned short*)&ll;
    }
    size_t rb = (size_t)row * 2048;
    *(ushort4*)&dst[rb + kq] = hp;
    *(ushort4*)&dst[rb + 1024 + kq] = lp;
}

// ---------------------------------------------------------------------------
// fp32 -> fp16 plain convert (weights)
// ---------------------------------------------------------------------------
__global__ void w16_kernel(const float* __restrict__ src,
                           __half* __restrict__ dst, int n4)
{
    int i = blockIdx.x * blockDim.x + threadIdx.x;
    if (i >= n4) return;
    float4 v = *(const float4*)&src[(size_t)i * 4];
    ushort4 hp;
    unsigned short* h = (unsigned short*)&hp;
    __half h0 = __float2half_rn(v.x); h[0] = *(unsigned short*)&h0;
    __half h1 = __float2half_rn(v.y); h[1] = *(unsigned short*)&h1;
    __half h2 = __float2half_rn(v.z); h[2] = *(unsigned short*)&h2;
    __half h3 = __float2half_rn(v.w); h[3] = *(unsigned short*)&h3;
    *(ushort4*)&dst[(size_t)i * 4] = hp;
}

// ---------------------------------------------------------------------------
// HMMA fp16 2-term GEMM: Y[M,1024] = (hi+lo)[M,2048] @ W16^T.
// Effective K = 2048; 32 chunks of 64. 3 stages, 1 sync/iter.
// QKV=1: ws=by/8 -> Wq/Wk/Wv; V (ws==2) written single fp16 to g_Vc;
//        Q/K fp32 head layout.  QKV=0: fp32 row-major.
// ---------------------------------------------------------------------------
#define ROWB2 144
#define OPST (128*ROWB2)
#define STG2 (2*OPST)
#define GSMEM (3*STG2)
#define NCH2 32

template<int QKV>
__global__ __launch_bounds__(256, 2)
void hmma_gemm(const __half* __restrict__ A,
               const __half* __restrict__ W0,
               const __half* __restrict__ W1,
               const __half* __restrict__ W2,
               float* __restrict__ Y0, float* __restrict__ Y1,
               float* __restrict__ Y2)
{
    extern __shared__ char smem[];
    const uint32_t sb = smem_u32(smem);
    const int tid = threadIdx.x;
    const int lane = tid & 31;
    const int w = tid >> 5;
    const int wm = w & 1, wn = w >> 1;

    const int m0 = blockIdx.x * 128;
    const int by = blockIdx.y;
    const int ws = QKV ? (by >> 3) : 0;
    const int nblk = by & 7;

    const __half* W = W0;
    float* Y = Y0;
    if (QKV) {
        if (ws == 1) { W = W1; Y = Y1; }
        else if (ws == 2) { W = W2; Y = Y2; }
    }

    const int lrow = tid >> 1;
    const int lhalf = (tid & 1) * 32;
    const __half* Asrc = A + (size_t)(m0 + lrow) * 2048 + lhalf;
    const __half* Wsrc = W + (size_t)(nblk * 128 + lrow) * 1024 + lhalf;
    const uint32_t dstA = sb + lrow * ROWB2 + lhalf * 2;
    const uint32_t dstW = dstA + OPST;

    float c[4][4][4];
#pragma unroll
    for (int i = 0; i < 4; i++)
#pragma unroll
        for (int j = 0; j < 4; j++)
#pragma unroll
            for (int q = 0; q < 4; q++) c[i][j][q] = 0.f;

    // chunk cc (0..31): A k-offset cc*64 (linear over hi|lo), W (cc&15)*64
#define C2_KA(cc) ((cc) * 64)
#define C2_KW(cc) (((cc) & 15) * 64)

#pragma unroll
    for (int s = 0; s < 2; s++) {
        int kA = C2_KA(s), kW = C2_KW(s);
        uint32_t so = s * STG2;
#pragma unroll
        for (int q = 0; q < 4; q++) {
            CP_ASYNC16(dstA + so + q * 16, Asrc + kA + q * 8);
            CP_ASYNC16(dstW + so + q * 16, Wsrc + kW + q * 8);
        }
        CP_COMMIT();
    }

    const uint32_t aLd = sb + (wm * 64 + (lane & 15)) * ROWB2 + (lane >> 4) * 16;
    const uint32_t bLd = sb + OPST +
        (wn * 32 + (lane & 7) + ((lane >> 4) & 1) * 8) * ROWB2 + ((lane >> 3) & 1) * 16;

    int stage = 0;
    for (int cc = 0; cc < NCH2; cc++) {
        CP_WAIT1();
        __syncthreads();
        if (cc + 2 < NCH2) {
            int sn = stage + 2; if (sn >= 3) sn -= 3;
            int kA = C2_KA(cc + 2), kW = C2_KW(cc + 2);
            uint32_t so = sn * STG2;
#pragma unroll
            for (int q = 0; q < 4; q++) {
                CP_ASYNC16(dstA + so + q * 16, Asrc + kA + q * 8);
                CP_ASYNC16(dstW + so + q * 16, Wsrc + kW + q * 8);
            }
        }
        CP_COMMIT();

        const uint32_t so = stage * STG2;
#pragma unroll
        for (int kh = 0; kh < 4; kh++) {
            uint32_t a[4][4], b[4][2];
#pragma unroll
            for (int mt = 0; mt < 4; mt++)
                LDM_X4(a[mt][0], a[mt][1], a[mt][2], a[mt][3],
                       aLd + so + mt * 16 * ROWB2 + kh * 32);
#pragma unroll
            for (int p = 0; p < 2; p++)
                LDM_X4(b[2*p][0], b[2*p][1], b[2*p+1][0], b[2*p+1][1],
                       bLd + so + p * 16 * ROWB2 + kh * 32);
#pragma unroll
            for (int mt = 0; mt < 4; mt++)
#pragma unroll
                for (int nt = 0; nt < 4; nt++)
                    MMA16816(c[mt][nt], a[mt], b[nt]);
        }
        stage = (stage == 2) ? 0 : stage + 1;
    }

#pragma unroll
    for (int mt = 0; mt < 4; mt++) {
        int mrow = m0 + wm * 64 + mt * 16 + (lane >> 2);
#pragma unroll
        for (int nt = 0; nt < 4; nt++) {
            int n = nblk * 128 + wn * 32 + nt * 8 + (lane & 3) * 2;
            if (QKV) {
                int h = n >> 6, d0 = n & 63;
                int b = mrow >> 11, s = mrow & (SEQ - 1);
                if (ws == 2) {
                    // V: single fp16 direct to g_Vc [row][64]
                    __half* dst = (__half*)Y +
                        (((size_t)((b << 4) + h) * SEQ + s) * 64 + d0);
                    *(uint32_t*)dst = packh(c[mt][nt][0], c[mt][nt][1]);
                    *(uint32_t*)(dst + 8 * 64) = packh(c[mt][nt][2], c[mt][nt][3]);
                } else {
                    float* dst = Y + (((size_t)((b << 4) + h) * SEQ + s) * DH + d0);
                    *(float2*)dst = make_float2(c[mt][nt][0], c[mt][nt][1]);
                    *(float2*)(dst + 8 * DH) = make_float2(c[mt][nt][2], c[mt][nt][3]);
                }
            } else {
                float* dst = Y + (size_t)mrow * 1024 + n;
                *(float2*)dst = make_float2(c[mt][nt][0], c[mt][nt][1]);
                *(float2*)(dst + 8 * 1024) = make_float2(c[mt][nt][2], c[mt][nt][3]);
            }
        }
    }
}

// ---------------------------------------------------------------------------
// Tensor-core flash attention (causal), fp16 2-term.
// Q hi/lo [row][128]; K/V single fp16 [row][64].
// ---------------------------------------------------------------------------
#define AROWB 272                       // Q row: 256B data + 16
#define KROWB 144                       // K/V row: 128B data + 16
#define QBYTES (128*AROWB)              // 34816
#define KVB (64*KROWB)                  // 9216
#define ASTAGE (2*KVB)                  // 18432
#define ATT_SMEM (QBYTES + 2*ASTAGE)    // 71680

__global__ __launch_bounds__(256)
void attn_mma_kernel()
{
    extern __shared__ char smem[];
    const uint32_t sb = smem_u32(smem);
    const uint32_t Qs = sb;
    const uint32_t St0 = sb + QBYTES;

    const int qt = blockIdx.x;
    const int bh = blockIdx.y;
    const int q0 = qt * 128;
    const int b = bh >> 4, h = bh & 15;

    const int tid = threadIdx.x;
    const int lane = tid & 31;
    const int w = tid >> 5;

    const char* Qg = (const char*)(g_Qc + ((size_t)bh * SEQ + q0) * 128);
    const char* Kg = (const char*)(g_Kc + (size_t)bh * SEQ * 64);
    const char* Vg = (const char*)(g_Vc + (size_t)bh * SEQ * 64);

    // Q tile: 128 rows x 256B
#pragma unroll
    for (int i = 0; i < 8; i++) {
        int idx = tid + i * 256;
        int r = idx >> 4, ch = (idx & 15) * 16;
        CP_ASYNC16(Qs + r * AROWB + ch, Qg + r * 256 + ch);
    }
    // KV tile 0: K/V 64 rows x 128B each
#pragma unroll
    for (int i = 0; i < 4; i++) {
        int idx = tid + i * 256;
        if (idx < 512) {
            int r = idx >> 3, ch = (idx & 7) * 16;
            CP_ASYNC16(St0 + r * KROWB + ch, Kg + r * 128 + ch);
        } else {
            int j = idx - 512;
            int r = j >> 3, ch = (j & 7) * 16;
            CP_ASYNC16(St0 + KVB + r * KROWB + ch, Vg + r * 128 + ch);
        }
    }
    CP_COMMIT();

    float of[8][4];
#pragma unroll
    for (int i = 0; i < 8; i++)
#pragma unroll
        for (int q = 0; q < 4; q++) of[i][q] = 0.f;
    float m0r = -1e30f, m1r = -1e30f, l0r = 0.f, l1r = 0.f;
    uint32_t qh[4][4], ql[4][4];

    const uint32_t qLd = Qs + (w * 16 + (lane & 15)) * AROWB + (lane >> 4) * 16;
    const uint32_t kRow = ((lane >> 4) & 1) * 8 + (lane & 7);
    const uint32_t kCol = ((lane >> 3) & 1) * 16;
    const uint32_t vRow = ((lane >> 3) & 1) * 8 + (lane & 7);
    const uint32_t vCol = ((lane >> 4) & 1) * 16;

    const int g = lane >> 2;
    const int cq = (lane & 3) * 2;
    const int wrow = q0 + w * 16;
    const int row0 = wrow + g;
    const int row1 = row0 + 8;

    const int nt = qt * 2 + 2;
    for (int t = 0; t < nt; t++) {
        if (t + 1 < nt) {
            const uint32_t stN = St0 + ((t + 1) & 1) * ASTAGE;
            const char* Kn = Kg + (size_t)(t + 1) * 64 * 128;
            const char* Vn = Vg + (size_t)(t + 1) * 64 * 128;
#pragma unroll
            for (int i = 0; i < 4; i++) {
                int idx = tid + i * 256;
                if (idx < 512) {
                    int r = idx >> 3, ch = (idx & 7) * 16;
                    CP_ASYNC16(stN + r * KROWB + ch, Kn + r * 128 + ch);
                } else {
                    int j = idx - 512;
                    int r = j >> 3, ch = (j & 7) * 16;
                    CP_ASYNC16(stN + KVB + r * KROWB + ch, Vn + r * 128 + ch);
                }
            }
        }
        CP_COMMIT();
        CP_WAIT1();
        __syncthreads();

        if (t == 0) {
#pragma unroll
            for (int ks = 0; ks < 4; ks++) {
                LDM_X4(qh[ks][0], qh[ks][1], qh[ks][2], qh[ks][3], qLd + ks * 32);
                LDM_X4(ql[ks][0], ql[ks][1], ql[ks][2], ql[ks][3], qLd + 128 + ks * 32);
            }
        }

        const int j0 = t * 64;
        if (j0 <= wrow + 15) {
            const uint32_t stK = St0 + (t & 1) * ASTAGE;
            const uint32_t stV = stK + KVB;
            const uint32_t kLd = stK + kRow * KROWB + kCol;
            const uint32_t vLd = stV + vRow * KROWB + vCol;

            float sc[8][4];
#pragma unroll
            for (int i = 0; i < 8; i++)
#pragma unroll
                for (int q = 0; q < 4; q++) sc[i][q] = 0.f;

#pragma unroll
            for (int ks = 0; ks < 4; ks++) {
                uint32_t bk[8][2];
#pragma unroll
                for (int p = 0; p < 4; p++)
                    LDM_X4(bk[2*p][0], bk[2*p][1], bk[2*p+1][0], bk[2*p+1][1],
                           kLd + p * 16 * KROWB + ks * 32);
#pragma unroll
                for (int nb = 0; nb < 8; nb++) {
                    MMA16816(sc[nb], qh[ks], bk[nb]);
                    MMA16816(sc[nb], ql[ks], bk[nb]);
                }
            }

            const bool domask = (j0 + 63 > wrow);
#pragma unroll
            for (int nb = 0; nb < 8; nb++) {
                int col = j0 + nb * 8 + cq;
#pragma unroll
                for (int q = 0; q < 4; q++) sc[nb][q] *= 0.125f;
                if (domask) {
                    if (col     > row0) sc[nb][0] = -1e30f;
                    if (col + 1 > row0) sc[nb][1] = -1e30f;
                    if (col     > row1) sc[nb][2] = -1e30f;
                    if (col + 1 > row1) sc[nb][3] = -1e30f;
                }
            }

            float mx0 = -1e30f, mx1 = -1e30f;
#pragma unroll
            for (int nb = 0; nb < 8; nb++) {
                mx0 = fmaxf(mx0, fmaxf(sc[nb][0], sc[nb][1]));
                mx1 = fmaxf(mx1, fmaxf(sc[nb][2], sc[nb][3]));
            }
            mx0 = fmaxf(mx0, __shfl_xor_sync(0xffffffffu, mx0, 1));
            mx0 = fmaxf(mx0, __shfl_xor_sync(0xffffffffu, mx0, 2));
            mx1 = fmaxf(mx1, __shfl_xor_sync(0xffffffffu, mx1, 1));
            mx1 = fmaxf(mx1, __shfl_xor_sync(0xffffffffu, mx1, 2));

            float mn0 = fmaxf(m0r, mx0), mn1 = fmaxf(m1r, mx1);
            float al0 = __expf(m0r - mn0), al1 = __expf(m1r - mn1);
            m0r = mn0; m1r = mn1;

            float rs0 = 0.f, rs1 = 0.f;
#pragma unroll
            for (int nb = 0; nb < 8; nb++) {
                sc[nb][0] = __expf(sc[nb][0] - mn0);
                sc[nb][1] = __expf(sc[nb][1] - mn0);
                sc[nb][2] = __expf(sc[nb][2] - mn1);
                sc[nb][3] = __expf(sc[nb][3] - mn1);
                rs0 += sc[nb][0] + sc[nb][1];
                rs1 += sc[nb][2] + sc[nb][3];
            }
            rs0 += __shfl_xor_sync(0xffffffffu, rs0, 1);
            rs0 += __shfl_xor_sync(0xffffffffu, rs0, 2);
            rs1 += __shfl_xor_sync(0xffffffffu, rs1, 1);
            rs1 += __shfl_xor_sync(0xffffffffu, rs1, 2);
            l0r = l0r * al0 + rs0;
            l1r = l1r * al1 + rs1;

#pragma unroll
            for (int i = 0; i < 8; i++) {
                of[i][0] *= al0; of[i][1] *= al0;
                of[i][2] *= al1; of[i][3] *= al1;
            }

#pragma unroll
            for (int ks = 0; ks < 4; ks++) {
                uint32_t aPh[4], aPl[4];
                float* s0 = sc[2 * ks];
                float* s1 = sc[2 * ks + 1];
                aPh[0] = packh(s0[0], s0[1]);
                aPh[1] = packh(s0[2], s0[3]);
                aPh[2] = packh(s1[0], s1[1]);
                aPh[3] = packh(s1[2], s1[3]);
#pragma unroll
                for (int q = 0; q < 4; q++) {
                    float* sp = (q < 2) ? s0 : s1;
                    int o2 = (q & 1) * 2;
                    __half2 h2 = *(__half2*)&aPh[q];
                    aPl[q] = packh(sp[o2] - __low2float(h2),
                                   sp[o2 + 1] - __high2float(h2));
                }
#pragma unroll
                for (int p = 0; p < 4; p++) {
                    uint32_t vh[4];
                    LDM_X4_T(vh[0], vh[1], vh[2], vh[3],
                             vLd + ks * 16 * KROWB + p * 32);
                    MMA16816(of[2*p],     aPh, vh);
                    MMA16816(of[2*p + 1], aPh, vh + 2);
                    MMA16816(of[2*p],     aPl, vh);
                    MMA16816(of[2*p + 1], aPl, vh + 2);
                }
            }
        }
        __syncthreads();
    }

    // epilogue: fp16 hi/lo direct to g_Acat [token_row][hi1024 | lo1024]
    float inv0 = 1.f / l0r, inv1 = 1.f / l1r;
    __half* ar0 = g_Acat + ((size_t)(b * SEQ + row0)) * 2048 + h * 64;
    __half* ar1 = g_Acat + ((size_t)(b * SEQ + row1)) * 2048 + h * 64;
#pragma unroll
    for (int nb = 0; nb < 8; nb++) {
        int d = nb * 8 + cq;
        float v0 = of[nb][0] * inv0, v1 = of[nb][1] * inv0;
        uint32_t hp = packh(v0, v1);
        __half2 hh = *(__half2*)&hp;
        uint32_t lp = packh(v0 - __low2float(hh), v1 - __high2float(hh));
        *(uint32_t*)(ar0 + d) = hp;
        *(uint32_t*)(ar0 + 1024 + d) = lp;
        float v2 = of[nb][2] * inv1, v3 = of[nb][3] * inv1;
        uint32_t hp1 = packh(v2, v3);
        __half2 hh1 = *(__half2*)&hp1;
        uint32_t lp1 = packh(v2 - __low2float(hh1), v3 - __high2float(hh1));
        *(uint32_t*)(ar1 + d) = hp1;
        *(uint32_t*)(ar1 + 1024 + d) = lp1;
    }
}

// ---------------------------------------------------------------------------
// Launch
// ---------------------------------------------------------------------------
extern "C" void kernel_launch(void* const* d_in, const int* in_sizes, int n_in,
                              void* d_out, int out_size)
{
    const float* x  = (const float*)d_in[0];
    const float* Wq = (const float*)d_in[2];
    const float* Wk = (const float*)d_in[3];
    const float* Wv = (const float*)d_in[4];
    const float* Wo = (const float*)d_in[5];
    float* out = (float*)d_out;

    float *qp, *kp;
    cudaGetSymbolAddress((void**)&qp, g_Q);
    cudaGetSymbolAddress((void**)&kp, g_K);
    void *xc, *ac, *wq16, *wk16, *wv16, *wo16, *vc;
    cudaGetSymbolAddress(&xc, g_Xcat);
    cudaGetSymbolAddress(&ac, g_Acat);
    cudaGetSymbolAddress(&wq16, g_Wq16);
    cudaGetSymbolAddress(&wk16, g_Wk16);
    cudaGetSymbolAddress(&wv16, g_Wv16);
    cudaGetSymbolAddress(&wo16, g_Wo16);
    cudaGetSymbolAddress(&vc, g_Vc);

    rope_table_kernel<<<(SEQ * 32 + 255) / 256, 256>>>();

    split_kernel<<<(MTOT * 256 + 255) / 256, 256>>>(x, (__half*)xc, MTOT * 256);
    w16_kernel<<<(1024 * 256 + 255) / 256, 256>>>(Wq, (__half*)wq16, 1024 * 256);
    w16_kernel<<<(1024 * 256 + 255) / 256, 256>>>(Wk, (__half*)wk16, 1024 * 256);
    w16_kernel<<<(1024 * 256 + 255) / 256, 256>>>(Wv, (__half*)wv16, 1024 * 256);
    w16_kernel<<<(1024 * 256 + 255) / 256, 256>>>(Wo, (__half*)wo16, 1024 * 256);

    cudaFuncSetAttribute(hmma_gemm<1>, cudaFuncAttributeMaxDynamicSharedMemorySize, GSMEM);
    cudaFuncSetAttribute(hmma_gemm<0>, cudaFuncAttributeMaxDynamicSharedMemorySize, GSMEM);

    hmma_gemm<1><<<dim3(MTOT / 128, 24), 256, GSMEM>>>(
        (const __half*)xc, (const __half*)wq16,
        (const __half*)wk16, (const __half*)wv16,
        qp, kp, (float*)vc);

    int nth = BH * SEQ * 8;
    rope_split_kernel<<<(nth + 255) / 256, 256>>>();

    cudaFuncSetAttribute(attn_mma_kernel,
                         cudaFuncAttributeMaxDynamicSharedMemorySize, ATT_SMEM);
    attn_mma_kernel<<<dim3(SEQ / 128, BH), 256, ATT_SMEM>>>();

    hmma_gemm<0><<<dim3(MTOT / 128, 8), 256, GSMEM>>>(
        (const __half*)ac, (const __half*)wo16,
        nullptr, nullptr, out, nullptr, nullptr);
}